// round 14
// baseline (speedup 1.0000x reference)
#include <cuda_runtime.h>
#include <cuda_bf16.h>
#include <math.h>

#define NN 65536
#define NE 262144
#define DD 256
#define D2 512
#define CHID 20

// pre-split weight buffer offsets (in words)
#define WOFF_WALL 0
#define WOFF_W1   16384
#define WOFF_W2   212992
#define WTOTAL    409600

// ------------------------- scratch (static device memory) -------------------
__device__ float g_x[NN * DD];
__device__ float g_h[NN * DD];          // z2 / h carrier between layers
__device__ float g_z1[NN * D2];
__device__ float g_agg[NN * DD];
__device__ float g_kappa[NN];
__device__ float g_f[3 * NN];
__device__ float g_fnacc[12 * NN];
__device__ float g_weights[NE];
__device__ float g_ew[NE];
__device__ float g_Wall[DD * 128];
__device__ float g_ball[128];
__device__ float4 g_W2p[128];           // packed second-layer heads (kappa,f0,f1,f2)
__device__ float g_b2p[4];
__device__ float g_h1raw[64];
__device__ float g_bnsum[D2];
__device__ float g_bnsq[D2];
__device__ float g_scale[D2];           // z1 BN
__device__ float g_bias[D2];
__device__ float g_scale2[DD];          // z2 BN
__device__ float g_bias2[DD];
__device__ float g_kapsum;
__device__ float g_loss;
__device__ unsigned g_hist[256];
__device__ unsigned g_prefix;
__device__ int g_rank;
__device__ int g_deg[NN];
__device__ int g_off[NN + 1];
__device__ int g_cur[NN];
__device__ int g_csr[NE];
__device__ __align__(16) unsigned g_Bh[WTOTAL];
__device__ __align__(16) unsigned g_Bl[WTOTAL];

__device__ __forceinline__ float sigmoidf_(float v) { return 1.0f / (1.0f + expf(-v)); }

// split-bf16: pack two adjacent-k fp32 values into bf16x2 hi and lo words
__device__ __forceinline__ void split2(float x, float y, unsigned &hi, unsigned &lo) {
    __nv_bfloat16 hx = __float2bfloat16_rn(x);
    __nv_bfloat16 hy = __float2bfloat16_rn(y);
    hi = ((unsigned)__bfloat16_as_ushort(hy) << 16) | (unsigned)__bfloat16_as_ushort(hx);
    float lx = x - __bfloat162float(hx);
    float ly = y - __bfloat162float(hy);
    __nv_bfloat16 ox = __float2bfloat16_rn(lx);
    __nv_bfloat16 oy = __float2bfloat16_rn(ly);
    lo = ((unsigned)__bfloat16_as_ushort(oy) << 16) | (unsigned)__bfloat16_as_ushort(ox);
}
__device__ __forceinline__ void mma16(float* c, const unsigned* a, const unsigned* b) {
    asm volatile("mma.sync.aligned.m16n8k16.row.col.f32.bf16.bf16.f32 "
        "{%0,%1,%2,%3}, {%4,%5,%6,%7}, {%8,%9}, {%0,%1,%2,%3};"
        : "+f"(c[0]), "+f"(c[1]), "+f"(c[2]), "+f"(c[3])
        : "r"(a[0]), "r"(a[1]), "r"(a[2]), "r"(a[3]), "r"(b[0]), "r"(b[1]));
}
__device__ __forceinline__ void cp16(void* s, const void* g) {
    unsigned saddr = (unsigned)__cvta_generic_to_shared(s);
    asm volatile("cp.async.cg.shared.global [%0], [%1], 16;\n" :: "r"(saddr), "l"(g));
}

// ------------------------------- init kernel --------------------------------
__global__ void k_zero_init() {
    int b = blockIdx.x, t = threadIdx.x;
    if (b < 256) {
        g_deg[b * 256 + t] = 0;
    } else {
        if (t < 64) g_h1raw[t] = 0.f;
        g_hist[t] = 0;
        g_bnsum[t] = 0.f; g_bnsq[t] = 0.f;
        g_bnsum[t + 256] = 0.f; g_bnsq[t + 256] = 0.f;
    }
}
__global__ void k_zero_fnacc() {
    int i = blockIdx.x * blockDim.x + threadIdx.x;
    for (; i < 12 * NN; i += gridDim.x * blockDim.x) g_fnacc[i] = 0.f;
}

// ------------------------------- CSR build ----------------------------------
__global__ void k_deg(const int* __restrict__ ei) {
    int e = blockIdx.x * blockDim.x + threadIdx.x;
    atomicAdd(&g_deg[ei[NE + e]], 1);
}
__global__ void k_scan() {
    __shared__ int part[1024];
    int t = threadIdx.x;
    int base = t * 64;
    int s = 0;
#pragma unroll 8
    for (int i = 0; i < 64; i++) s += g_deg[base + i];
    part[t] = s;
    __syncthreads();
    for (int d = 1; d < 1024; d <<= 1) {
        int v = (t >= d) ? part[t - d] : 0;
        __syncthreads();
        part[t] += v;
        __syncthreads();
    }
    int run = part[t] - s;
    for (int i = 0; i < 64; i++) {
        g_off[base + i] = run;
        g_cur[base + i] = run;
        run += g_deg[base + i];
    }
    if (t == 1023) g_off[NN] = run;
}
__global__ void k_fill(const int* __restrict__ ei) {
    int e = blockIdx.x * blockDim.x + threadIdx.x;
    int d = ei[NE + e];
    int pos = atomicAdd(&g_cur[d], 1);
    g_csr[pos] = e;
}

// ------------------------------- atom embedding -----------------------------
__global__ void k_embed(const int* __restrict__ xa, const float* __restrict__ emb) {
    int n = blockIdx.x * 8 + (threadIdx.x >> 5);
    int lane = threadIdx.x & 31;
    float4 a0 = make_float4(0.f, 0.f, 0.f, 0.f);
    float4 a1 = make_float4(0.f, 0.f, 0.f, 0.f);
#pragma unroll
    for (int f = 0; f < 9; f++) {
        int v = xa[n * 9 + f];
        const float4* row = (const float4*)(emb + ((size_t)(f * 128 + v)) * DD);
        float4 b0 = row[lane * 2], b1 = row[lane * 2 + 1];
        a0.x += b0.x; a0.y += b0.y; a0.z += b0.z; a0.w += b0.w;
        a1.x += b1.x; a1.y += b1.y; a1.z += b1.z; a1.w += b1.w;
    }
    float4* out = (float4*)(g_x + (size_t)n * DD);
    out[lane * 2] = a0; out[lane * 2 + 1] = a1;
}

// ------- pack the 4 small-MLP first layers into [256,128] + head pack -------
__global__ void k_packW(const float* __restrict__ cw1, const float* __restrict__ cb1,
                        const float* __restrict__ fw1, const float* __restrict__ fb1,
                        const float* __restrict__ cw2, const float* __restrict__ cb2,
                        const float* __restrict__ fw2, const float* __restrict__ fb2) {
    int idx = blockIdx.x * blockDim.x + threadIdx.x;
    if (idx >= DD * 128) return;
    int k = idx >> 7, u = idx & 127;
    float v = 0.f;
    if (u < CHID) v = cw1[k * CHID + u];
    else if (u < 80) {
        int i = (u - CHID) / CHID, j = (u - CHID) % CHID;
        v = fw1[((size_t)i * DD + k) * CHID + j];
    }
    g_Wall[idx] = v;
    if (k == 0) {
        float b = 0.f;
        if (u < CHID) b = cb1[u];
        else if (u < 80) { int i = (u - CHID) / CHID, j = (u - CHID) % CHID; b = fb1[i * CHID + j]; }
        g_ball[u] = b;
        // pack second-layer heads: col u contributes to exactly one of 4 outputs
        float4 wp = make_float4(0.f, 0.f, 0.f, 0.f);
        if (u < 20) wp.x = cw2[u];
        else if (u < 40) wp.y = fw2[0 * CHID + (u - 20)];
        else if (u < 60) wp.z = fw2[1 * CHID + (u - 40)];
        else if (u < 80) wp.w = fw2[2 * CHID + (u - 60)];
        g_W2p[u] = wp;
        if (u == 0) {
            g_b2p[0] = cb2[0];
            g_b2p[1] = fb2[0]; g_b2p[2] = fb2[1]; g_b2p[3] = fb2[2];
            g_kapsum = 0.f; g_loss = 0.f;
        }
    }
}

// ------ pre-split ALL weight matrices into swizzled bf16 hi/lo layout -------
// word (n, ktile, c) at dst[n*(K/2) + ktile*8 + c] where column c holds
// kpair p = ((c&1)<<2) | (((c>>1) ^ (n&3)) & 3)
__global__ void k_presplit_all(const float* __restrict__ gw1, const float* __restrict__ gw2) {
    int id = blockIdx.x * blockDim.x + threadIdx.x;
    if (id >= WTOTAL) return;
    const float* src;
    int K, Nc, rem;
    if (id < WOFF_W1) {
        src = g_Wall; K = 256; Nc = 128; rem = id;
    } else if (id < WOFF_W2) {
        int rid = id - WOFF_W1;
        int l = rid >> 16; rem = rid & 65535;
        src = gw1 + (size_t)l * (DD * D2); K = 256; Nc = 512;
    } else {
        int rid = id - WOFF_W2;
        int l = rid >> 16; rem = rid & 65535;
        src = gw2 + (size_t)l * (D2 * DD); K = 512; Nc = 256;
    }
    int kw = K >> 1;
    int n = rem / kw, r2 = rem - n * kw;
    int kt = r2 >> 3, c = r2 & 7;
    int p = ((c & 1) << 2) | (((c >> 1) ^ n) & 3);
    int k0 = kt * 16 + 2 * p;
    unsigned hi, lo;
    split2(src[(size_t)k0 * Nc + n], src[(size_t)(k0 + 1) * Nc + n], hi, lo);
    g_Bh[id] = hi;
    g_Bl[id] = lo;
}

// ------------- split-bf16 (3-term, ~fp32) tensor-core GEMM ------------------
// AMODE 0: A=g_x (MLP);  1: alpha*g_x+g_agg;  2: relu(z1*sc+bb);
// AMODE 3: alpha*relu(g_h*sc2+bb2)+g_agg
template <int AMODE>
__device__ __forceinline__ float4 loadA_t(const float* __restrict__ A, size_t rowoff,
                                          int col, float alpha) {
    float4 va = *(const float4*)(A + rowoff + col);
    if (AMODE == 1) {
        float4 w = *(const float4*)(g_agg + rowoff + col);
        va.x = alpha * va.x + w.x; va.y = alpha * va.y + w.y;
        va.z = alpha * va.z + w.z; va.w = alpha * va.w + w.w;
    }
    if (AMODE == 2) {
        float4 sc = *(const float4*)(g_scale + col);
        float4 bb = *(const float4*)(g_bias + col);
        va.x = fmaxf(va.x * sc.x + bb.x, 0.f);
        va.y = fmaxf(va.y * sc.y + bb.y, 0.f);
        va.z = fmaxf(va.z * sc.z + bb.z, 0.f);
        va.w = fmaxf(va.w * sc.w + bb.w, 0.f);
    }
    if (AMODE == 3) {
        float4 sc = *(const float4*)(g_scale2 + col);
        float4 bb = *(const float4*)(g_bias2 + col);
        float4 w = *(const float4*)(g_agg + rowoff + col);
        va.x = alpha * fmaxf(va.x * sc.x + bb.x, 0.f) + w.x;
        va.y = alpha * fmaxf(va.y * sc.y + bb.y, 0.f) + w.y;
        va.z = alpha * fmaxf(va.z * sc.z + bb.z, 0.f) + w.z;
        va.w = alpha * fmaxf(va.w * sc.w + bb.w, 0.f) + w.w;
    }
    return va;
}

template <int AMODE, bool RELU, bool STATS, bool MLPEPI>
__global__ __launch_bounds__(256, 2) void k_gemm_tc(int Asel,
        int Boff, const float* __restrict__ biasp,
        const float* __restrict__ epsp, int Csel, int Nc, int K) {
    __shared__ unsigned Ahs[2][128][8], Als[2][128][8];
    __shared__ unsigned Bhs[2][128][8], Bls[2][128][8];
    __shared__ float sredS[128], sredQ[128];

    const float* A;
    if (AMODE == 0) A = g_x;
    else if (AMODE == 1) A = (Asel == 0) ? g_x : g_h;
    else if (AMODE == 3) A = g_h;
    else A = g_z1;
    const float* bias = (AMODE == 0) ? g_ball : biasp;
    float* C = (Csel == 0) ? g_z1 : ((Csel == 1) ? g_agg : g_h);
    float alpha = (AMODE == 1 || AMODE == 3) ? (1.0f + epsp[0]) : 0.f;

    int tid = threadIdx.x;
    int bm = blockIdx.y * 128, bn = blockIdx.x * 128;
    if (STATS && tid < 128) { sredS[tid] = 0.f; sredQ[tid] = 0.f; }

    int aRow = tid >> 2, aP0 = (tid & 3) * 2;
    int aCol0 = aP0 * 2;
    int r3f = aRow & 3;
    int cA0 = 2 * ((aP0 & 3) ^ r3f) + (aP0 >> 2);
    int cA1 = 2 * (((aP0 + 1) & 3) ^ r3f) + ((aP0 + 1) >> 2);
    size_t aoff0 = (size_t)(bm + aRow) * K;
    size_t aoff1 = (size_t)(bm + aRow + 64) * K;
    int nl = tid >> 1, halfB = (tid & 1) * 4;
    const unsigned* bhsrc = g_Bh + Boff + (size_t)(bn + nl) * (K >> 1) + halfB;
    const unsigned* blsrc = g_Bl + Boff + (size_t)(bn + nl) * (K >> 1) + halfB;

    int w = tid >> 5, lane = tid & 31;
    int wm = (w >> 1) * 32, wn = (w & 1) * 64;
    int qr = lane >> 2, qc = lane & 3;
    int j2 = 2 * (qc ^ (qr & 3));

    float acc[2][8][4];
#pragma unroll
    for (int mt = 0; mt < 2; mt++)
#pragma unroll
        for (int nt = 0; nt < 8; nt++)
#pragma unroll
            for (int j = 0; j < 4; j++) acc[mt][nt][j] = 0.f;

    float4 va0, va1;
    unsigned th, tl;

    cp16(&Bhs[0][nl][halfB], bhsrc);
    cp16(&Bls[0][nl][halfB], blsrc);
    asm volatile("cp.async.commit_group;\n");
    va0 = loadA_t<AMODE>(A, aoff0, aCol0, alpha);
    va1 = loadA_t<AMODE>(A, aoff1, aCol0, alpha);
    split2(va0.x, va0.y, th, tl); Ahs[0][aRow][cA0] = th; Als[0][aRow][cA0] = tl;
    split2(va0.z, va0.w, th, tl); Ahs[0][aRow][cA1] = th; Als[0][aRow][cA1] = tl;
    split2(va1.x, va1.y, th, tl); Ahs[0][aRow + 64][cA0] = th; Als[0][aRow + 64][cA0] = tl;
    split2(va1.z, va1.w, th, tl); Ahs[0][aRow + 64][cA1] = th; Als[0][aRow + 64][cA1] = tl;
    asm volatile("cp.async.wait_group 0;\n");
    __syncthreads();

    int buf = 0;
#pragma unroll 1
    for (int k0 = 0; k0 < K; k0 += 16) {
        int kn = k0 + 16;
        if (kn < K) {
            cp16(&Bhs[buf ^ 1][nl][halfB], bhsrc + (kn >> 1));
            cp16(&Bls[buf ^ 1][nl][halfB], blsrc + (kn >> 1));
            asm volatile("cp.async.commit_group;\n");
            va0 = loadA_t<AMODE>(A, aoff0, kn + aCol0, alpha);
            va1 = loadA_t<AMODE>(A, aoff1, kn + aCol0, alpha);
        }
        unsigned ah[2][4], al_[2][4];
#pragma unroll
        for (int mt = 0; mt < 2; mt++) {
            int r = wm + mt * 16 + qr;
            uint2 x0 = *(const uint2*)&Ahs[buf][r][j2];
            uint2 x1 = *(const uint2*)&Ahs[buf][r + 8][j2];
            ah[mt][0] = x0.x; ah[mt][1] = x1.x; ah[mt][2] = x0.y; ah[mt][3] = x1.y;
            uint2 y0 = *(const uint2*)&Als[buf][r][j2];
            uint2 y1 = *(const uint2*)&Als[buf][r + 8][j2];
            al_[mt][0] = y0.x; al_[mt][1] = y1.x; al_[mt][2] = y0.y; al_[mt][3] = y1.y;
        }
#pragma unroll
        for (int nt = 0; nt < 8; nt++) {
            int n = wn + nt * 8 + qr;
            uint2 bh2 = *(const uint2*)&Bhs[buf][n][j2];
            uint2 bl2 = *(const uint2*)&Bls[buf][n][j2];
            unsigned bhf[2] = {bh2.x, bh2.y};
            unsigned blf[2] = {bl2.x, bl2.y};
            mma16(acc[0][nt], ah[0], bhf);
            mma16(acc[1][nt], ah[1], bhf);
            mma16(acc[0][nt], ah[0], blf);
            mma16(acc[1][nt], ah[1], blf);
            mma16(acc[0][nt], al_[0], bhf);
            mma16(acc[1][nt], al_[1], bhf);
        }
        if (kn < K) {
            int nb = buf ^ 1;
            split2(va0.x, va0.y, th, tl); Ahs[nb][aRow][cA0] = th; Als[nb][aRow][cA0] = tl;
            split2(va0.z, va0.w, th, tl); Ahs[nb][aRow][cA1] = th; Als[nb][aRow][cA1] = tl;
            split2(va1.x, va1.y, th, tl); Ahs[nb][aRow + 64][cA0] = th; Als[nb][aRow + 64][cA0] = tl;
            split2(va1.z, va1.w, th, tl); Ahs[nb][aRow + 64][cA1] = th; Als[nb][aRow + 64][cA1] = tl;
            asm volatile("cp.async.wait_group 0;\n");
            __syncthreads();
            buf ^= 1;
        }
    }

    float psum[16], psq[16];
    if (STATS) {
#pragma unroll
        for (int j = 0; j < 16; j++) { psum[j] = 0.f; psq[j] = 0.f; }
    }
    float racc[4][4];
    if (MLPEPI) {
#pragma unroll
        for (int s = 0; s < 4; s++)
#pragma unroll
            for (int o = 0; o < 4; o++) racc[s][o] = 0.f;
    }
#pragma unroll
    for (int nt = 0; nt < 8; nt++) {
        int cc0 = wn + nt * 8 + qc * 2;
        int col0 = bn + cc0;
        float bv0 = bias[col0], bv1 = bias[col0 + 1];
#pragma unroll
        for (int mt = 0; mt < 2; mt++) {
            int row0 = bm + wm + mt * 16 + qr;
            float v00 = acc[mt][nt][0] + bv0;
            float v01 = acc[mt][nt][1] + bv1;
            float v10 = acc[mt][nt][2] + bv0;
            float v11 = acc[mt][nt][3] + bv1;
            if (RELU) {
                v00 = fmaxf(v00, 0.f); v01 = fmaxf(v01, 0.f);
                v10 = fmaxf(v10, 0.f); v11 = fmaxf(v11, 0.f);
            }
            if (STATS) {
                psum[nt * 2 + 0] += v00 + v10;
                psum[nt * 2 + 1] += v01 + v11;
                psq[nt * 2 + 0] += v00 * v00 + v10 * v10;
                psq[nt * 2 + 1] += v01 * v01 + v11 * v11;
            }
            if (MLPEPI) {
                float4 w0 = g_W2p[cc0], w1 = g_W2p[cc0 + 1];
                racc[mt * 2 + 0][0] += v00 * w0.x + v01 * w1.x;
                racc[mt * 2 + 0][1] += v00 * w0.y + v01 * w1.y;
                racc[mt * 2 + 0][2] += v00 * w0.z + v01 * w1.z;
                racc[mt * 2 + 0][3] += v00 * w0.w + v01 * w1.w;
                racc[mt * 2 + 1][0] += v10 * w0.x + v11 * w1.x;
                racc[mt * 2 + 1][1] += v10 * w0.y + v11 * w1.y;
                racc[mt * 2 + 1][2] += v10 * w0.z + v11 * w1.z;
                racc[mt * 2 + 1][3] += v10 * w0.w + v11 * w1.w;
            } else {
                *(float2*)(C + (size_t)row0 * Nc + col0) = make_float2(v00, v01);
                *(float2*)(C + (size_t)(row0 + 8) * Nc + col0) = make_float2(v10, v11);
            }
        }
    }
    if (MLPEPI) {
        // reduce over qc lanes (bits 0-1 of lane)
#pragma unroll
        for (int s = 0; s < 4; s++)
#pragma unroll
            for (int o = 0; o < 4; o++) {
                racc[s][o] += __shfl_xor_sync(0xffffffff, racc[s][o], 1);
                racc[s][o] += __shfl_xor_sync(0xffffffff, racc[s][o], 2);
            }
        __syncthreads();
        float* sred = (float*)&Ahs[0][0][0];   // 128 rows x 8 (2 halves x 4 outs)
        if ((lane & 3) == 0) {
#pragma unroll
            for (int s = 0; s < 4; s++) {
                int row = wm + (s >> 1) * 16 + qr + (s & 1) * 8;
#pragma unroll
                for (int o = 0; o < 4; o++)
                    sred[row * 8 + (w & 1) * 4 + o] = racc[s][o];
            }
        }
        __syncthreads();
        if (tid < 128) {
            float o0 = sred[tid * 8 + 0] + sred[tid * 8 + 4] + g_b2p[0];
            float o1 = sred[tid * 8 + 1] + sred[tid * 8 + 5] + g_b2p[1];
            float o2 = sred[tid * 8 + 2] + sred[tid * 8 + 6] + g_b2p[2];
            float o3 = sred[tid * 8 + 3] + sred[tid * 8 + 7] + g_b2p[3];
            int row = bm + tid;
            float kap = sigmoidf_(o0);
            g_kappa[row] = kap;
            g_f[row] = sigmoidf_(o1);
            g_f[NN + row] = sigmoidf_(o2);
            g_f[2 * NN + row] = sigmoidf_(o3);
            float kp = kap;
#pragma unroll
            for (int off = 16; off > 0; off >>= 1)
                kp += __shfl_xor_sync(0xffffffff, kp, off);
            if (lane == 0) atomicAdd(&g_kapsum, kp);
        }
    }
    if (STATS) {
#pragma unroll
        for (int j = 0; j < 16; j++) {
#pragma unroll
            for (int off = 4; off < 32; off <<= 1) {
                psum[j] += __shfl_xor_sync(0xffffffff, psum[j], off);
                psq[j] += __shfl_xor_sync(0xffffffff, psq[j], off);
            }
        }
        if (lane < 4) {
#pragma unroll
            for (int nt = 0; nt < 8; nt++) {
#pragma unroll
                for (int h = 0; h < 2; h++) {
                    int cl = wn + nt * 8 + lane * 2 + h;
                    atomicAdd(&sredS[cl], psum[nt * 2 + h]);
                    atomicAdd(&sredQ[cl], psq[nt * 2 + h]);
                }
            }
        }
        __syncthreads();
        if (tid < 128) {
            atomicAdd(&g_bnsum[bn + tid], sredS[tid]);
            atomicAdd(&g_bnsq[bn + tid], sredQ[tid]);
        }
    }
}

// ------------------------------- WeightMLP ----------------------------------
__global__ void k_wm_reduce(const int* __restrict__ ea, const float* __restrict__ w1) {
    __shared__ float sm[4][64];
    int t = threadIdx.x, g = t >> 6, j = t & 63;
    float acc = 0.f;
    for (int e = blockIdx.x * 4 + g; e < NE; e += gridDim.x * 4) {
        float s = (float)(ea[e * 3] + ea[e * 3 + 1] + ea[e * 3 + 2]);
        acc += s * w1[(size_t)e * 64 + j];
    }
    sm[g][j] = acc;
    __syncthreads();
    if (g == 0) atomicAdd(&g_h1raw[j], sm[0][j] + sm[1][j] + sm[2][j] + sm[3][j]);
}
__global__ void k_weights(const float* __restrict__ b1, const float* __restrict__ w2,
                          const float* __restrict__ b2, const float* __restrict__ w3,
                          const float* __restrict__ b3) {
    __shared__ float h1[64], h2[64];
    int t = threadIdx.x;
    if (t < 64) h1[t] = fmaxf(g_h1raw[t] + b1[t], 0.f);
    __syncthreads();
    if (t < 64) {
        float a = b2[t];
#pragma unroll 8
        for (int k = 0; k < 64; k++) a += h1[k] * w2[k * 64 + t];
        h2[t] = fmaxf(a, 0.f);
    }
    __syncthreads();
    int e = blockIdx.x * 256 + t;
    float acc = b3[e];
#pragma unroll 8
    for (int k = 0; k < 64; k++) acc += h2[k] * w3[(size_t)k * NE + e];
    g_weights[e] = sigmoidf_(acc);
}

// -------------------- exact top-k threshold (parallel radix) ----------------
__global__ void k_rinit(const int* __restrict__ pp) {
    long long nr = (long long)NN * (long long)pp[0] / 100;
    int r = (int)((nr < 100) ? nr : 100);
    if (r < 1) r = 1;
    g_rank = r;
    g_prefix = 0;
}
__global__ void k_hist(int pass) {
    __shared__ unsigned sh[256];
    int t = threadIdx.x;
    sh[t] = 0;
    __syncthreads();
    int shift = 24 - pass * 8;
    unsigned pfx = g_prefix;
    for (int i = blockIdx.x * 256 + t; i < NN; i += gridDim.x * 256) {
        unsigned bits = __float_as_uint(g_kappa[i]);
        bool ok = (pass == 0) || ((bits >> (shift + 8)) == (pfx >> (shift + 8)));
        if (ok) atomicAdd(&sh[(bits >> shift) & 255], 1u);
    }
    __syncthreads();
    if (sh[t]) atomicAdd(&g_hist[t], sh[t]);
}
__global__ void k_rsel(int pass) {
    __shared__ unsigned h[256];
    int t = threadIdx.x;
    h[t] = g_hist[t];
    g_hist[t] = 0;
    __syncthreads();
    if (t == 0) {
        int r = g_rank;
        unsigned d = 255;
        for (;; d--) {
            unsigned c = h[d];
            if (r <= (int)c || d == 0) break;
            r -= (int)c;
        }
        g_rank = r;
        g_prefix |= (d << (24 - pass * 8));
    }
}
__global__ void k_ew(const int* __restrict__ ei) {
    int e = blockIdx.x * blockDim.x + threadIdx.x;
    unsigned thr = g_prefix;
    unsigned a = __float_as_uint(g_kappa[ei[e]]);
    unsigned b = __float_as_uint(g_kappa[ei[NE + e]]);
    g_ew[e] = (a >= thr || b >= thr) ? 1e-5f : 1.0f;
}

// ----------------------- Bakry-Emery functional passes ----------------------
__global__ void k_fnA(const int* __restrict__ ei) {
    int e = blockIdx.x * blockDim.x + threadIdx.x;
    int s = ei[e], d = ei[NE + e];
    float w = g_weights[e];
#pragma unroll
    for (int i = 0; i < 3; i++) {
        float fd = g_f[i * NN + d] - g_f[i * NN + s];
        atomicAdd(&g_fnacc[i * NN + s], 0.5f * w * fd * fd);
        atomicAdd(&g_fnacc[3 * NN + i * NN + s], w * fd);
    }
}
__global__ void k_fnB(const int* __restrict__ ei) {
    int e = blockIdx.x * blockDim.x + threadIdx.x;
    int s = ei[e], d = ei[NE + e];
    float w = g_weights[e];
#pragma unroll
    for (int i = 0; i < 3; i++) {
        float gd = g_fnacc[i * NN + d] - g_fnacc[i * NN + s];
        atomicAdd(&g_fnacc[6 * NN + i * NN + s], w * gd);
        float fd = g_f[i * NN + d] - g_f[i * NN + s];
        float dfd = g_fnacc[3 * NN + i * NN + d] - g_fnacc[3 * NN + i * NN + s];
        atomicAdd(&g_fnacc[9 * NN + i * NN + s], 0.5f * w * fd * dfd);
    }
}
__global__ void k_fnC() {
    __shared__ float red[256];
    int n = blockIdx.x * 256 + threadIdx.x;
    float kap = g_kappa[n];
    float part = 0.f;
#pragma unroll
    for (int i = 0; i < 3; i++) {
        float gam = g_fnacc[i * NN + n];
        float dg = g_fnacc[6 * NN + i * NN + n];
        float gfd = g_fnacc[9 * NN + i * NN + n];
        part += fmaxf(kap * gam - (0.5f * dg - gfd), 0.f);
    }
    red[threadIdx.x] = part;
    __syncthreads();
    for (int s = 128; s > 0; s >>= 1) { if (threadIdx.x < s) red[threadIdx.x] += red[threadIdx.x + s]; __syncthreads(); }
    if (threadIdx.x == 0) atomicAdd(&g_loss, red[0]);
}

// ------- GIN message: CSR gather; HSEL=1 applies h=relu(BN2(z2)) on read ----
template <int HSEL>
__global__ void k_msg2(const int* __restrict__ ei, const int* __restrict__ ea,
                       const float* __restrict__ bemb) {
    const float* h = HSEL ? g_h : g_x;
    int n = blockIdx.x * 8 + (threadIdx.x >> 5);
    int lane = threadIdx.x & 31;
    int beg = g_off[n], end = g_off[n + 1];
    float4 a0 = make_float4(0.f, 0.f, 0.f, 0.f);
    float4 a1 = make_float4(0.f, 0.f, 0.f, 0.f);
    int q = lane * 2;
    float4 sc0, bb0, sc1, bb1;
    if (HSEL) {
        sc0 = ((const float4*)g_scale2)[q];     bb0 = ((const float4*)g_bias2)[q];
        sc1 = ((const float4*)g_scale2)[q + 1]; bb1 = ((const float4*)g_bias2)[q + 1];
    }
    for (int p = beg; p < end; p++) {
        int e = g_csr[p];
        int s = ei[e];
        float w = g_ew[e];
        const float4* b0 = (const float4*)(bemb + (size_t)(0 * 8 + ea[e * 3 + 0]) * DD);
        const float4* b1 = (const float4*)(bemb + (size_t)(1 * 8 + ea[e * 3 + 1]) * DD);
        const float4* b2 = (const float4*)(bemb + (size_t)(2 * 8 + ea[e * 3 + 2]) * DD);
        const float4* hs = (const float4*)(h + (size_t)s * DD);
        float4 v = hs[q];
        if (HSEL) {
            v.x = fmaxf(v.x * sc0.x + bb0.x, 0.f);
            v.y = fmaxf(v.y * sc0.y + bb0.y, 0.f);
            v.z = fmaxf(v.z * sc0.z + bb0.z, 0.f);
            v.w = fmaxf(v.w * sc0.w + bb0.w, 0.f);
        }
        float4 x0 = b0[q], x1 = b1[q], x2 = b2[q];
        a0.x += fmaxf(v.x + x0.x + x1.x + x2.x, 0.f) * w;
        a0.y += fmaxf(v.y + x0.y + x1.y + x2.y, 0.f) * w;
        a0.z += fmaxf(v.z + x0.z + x1.z + x2.z, 0.f) * w;
        a0.w += fmaxf(v.w + x0.w + x1.w + x2.w, 0.f) * w;
        v = hs[q + 1];
        if (HSEL) {
            v.x = fmaxf(v.x * sc1.x + bb1.x, 0.f);
            v.y = fmaxf(v.y * sc1.y + bb1.y, 0.f);
            v.z = fmaxf(v.z * sc1.z + bb1.z, 0.f);
            v.w = fmaxf(v.w * sc1.w + bb1.w, 0.f);
        }
        x0 = b0[q + 1]; x1 = b1[q + 1]; x2 = b2[q + 1];
        a1.x += fmaxf(v.x + x0.x + x1.x + x2.x, 0.f) * w;
        a1.y += fmaxf(v.y + x0.y + x1.y + x2.y, 0.f) * w;
        a1.z += fmaxf(v.z + x0.z + x1.z + x2.z, 0.f) * w;
        a1.w += fmaxf(v.w + x0.w + x1.w + x2.w, 0.f) * w;
    }
    float4* out = (float4*)(g_agg + (size_t)n * DD);
    out[q] = a0; out[q + 1] = a1;
}

// ----------------------------- BN final + apply -----------------------------
__global__ void k_bnfinal(const float* __restrict__ g, const float* __restrict__ b) {
    int c = threadIdx.x;
    float mean = g_bnsum[c] * (1.0f / NN);
    float var = g_bnsq[c] * (1.0f / NN) - mean * mean;
    float inv = rsqrtf(var + 1e-5f);
    float sc = g[c] * inv;
    g_scale[c] = sc;
    g_bias[c] = b[c] - mean * sc;
    g_bnsum[c] = 0.f;
    g_bnsq[c] = 0.f;
}
__global__ void k_bnfinal2(const float* __restrict__ g, const float* __restrict__ b) {
    int c = threadIdx.x;
    float mean = g_bnsum[c] * (1.0f / NN);
    float var = g_bnsq[c] * (1.0f / NN) - mean * mean;
    float inv = rsqrtf(var + 1e-5f);
    float sc = g[c] * inv;
    g_scale2[c] = sc;
    g_bias2[c] = b[c] - mean * sc;
    g_bnsum[c] = 0.f;
    g_bnsq[c] = 0.f;
}
__global__ void k_bnapply(float* __restrict__ dout) {
    int i = blockIdx.x * blockDim.x + threadIdx.x;
    float4 v = ((const float4*)g_h)[i];
    int cb = i & (DD / 4 - 1);
    float4 sc = ((const float4*)g_scale2)[cb];
    float4 bb = ((const float4*)g_bias2)[cb];
    v.x = v.x * sc.x + bb.x; v.y = v.y * sc.y + bb.y;
    v.z = v.z * sc.z + bb.z; v.w = v.w * sc.w + bb.w;
    ((float4*)dout)[i] = v;
}
__global__ void k_final(float* __restrict__ dout, int write) {
    if (write) dout[(size_t)NN * DD] = g_loss - 3.0f * g_kapsum;
}

// --------------------------------- launcher ---------------------------------
extern "C" void kernel_launch(void* const* d_in, const int* in_sizes, int n_in,
                              void* d_out, int out_size) {
    const int*   xa   = (const int*)d_in[0];
    const int*   ei   = (const int*)d_in[1];
    const int*   ea   = (const int*)d_in[2];
    const int*   pp   = (const int*)d_in[3];
    const float* aemb = (const float*)d_in[4];
    const float* bemb = (const float*)d_in[5];
    const float* gw1  = (const float*)d_in[6];
    const float* gb1  = (const float*)d_in[7];
    const float* gbng = (const float*)d_in[8];
    const float* gbnb = (const float*)d_in[9];
    const float* gw2  = (const float*)d_in[10];
    const float* gb2  = (const float*)d_in[11];
    const float* geps = (const float*)d_in[12];
    const float* bng  = (const float*)d_in[13];
    const float* bnb  = (const float*)d_in[14];
    const float* cw1  = (const float*)d_in[15];
    const float* cb1  = (const float*)d_in[16];
    const float* cw2  = (const float*)d_in[17];
    const float* cb2  = (const float*)d_in[18];
    const float* fw1  = (const float*)d_in[19];
    const float* fb1  = (const float*)d_in[20];
    const float* fw2  = (const float*)d_in[21];
    const float* fb2  = (const float*)d_in[22];
    const float* wmw1 = (const float*)d_in[23];
    const float* wmb1 = (const float*)d_in[24];
    const float* wmw2 = (const float*)d_in[25];
    const float* wmb2 = (const float*)d_in[26];
    const float* wmw3 = (const float*)d_in[27];
    const float* wmb3 = (const float*)d_in[28];
    float* out = (float*)d_out;

    // launches 1-3, then #4 = MLP GEMM (ncu captures launch #4)
    k_packW<<<(DD * 128 + 255) / 256, 256>>>(cw1, cb1, fw1, fb1, cw2, cb2, fw2, fb2);
    k_presplit_all<<<(WTOTAL + 255) / 256, 256>>>(gw1, gw2);
    k_embed<<<NN / 8, 256>>>(xa, aemb);
    k_gemm_tc<0, true, false, true><<<dim3(1, NN / 128), 256>>>(0, WOFF_WALL, nullptr, nullptr, 0, 128, DD);

    k_zero_init<<<257, 256>>>();
    k_deg<<<NE / 256, 256>>>(ei);
    k_scan<<<1, 1024>>>();
    k_fill<<<NE / 256, 256>>>(ei);
    k_wm_reduce<<<512, 256>>>(ea, wmw1);
    k_weights<<<NE / 256, 256>>>(wmb1, wmw2, wmb2, wmw3, wmb3);
    k_rinit<<<1, 1>>>(pp);
    for (int p = 0; p < 4; p++) {
        k_hist<<<64, 256>>>(p);
        k_rsel<<<1, 256>>>(p);
    }
    k_ew<<<NE / 256, 256>>>(ei);
    k_zero_fnacc<<<768, 256>>>();
    k_fnA<<<NE / 256, 256>>>(ei);
    k_fnB<<<NE / 256, 256>>>(ei);
    k_fnC<<<NN / 256, 256>>>();

    for (int l = 0; l < 3; l++) {
        if (l == 0)
            k_msg2<0><<<NN / 8, 256>>>(ei, ea, bemb + (size_t)l * 3 * 8 * DD);
        else
            k_msg2<1><<<NN / 8, 256>>>(ei, ea, bemb + (size_t)l * 3 * 8 * DD);
        if (l == 0)
            k_gemm_tc<1, false, true, false><<<dim3(D2 / 128, NN / 128), 256>>>(
                0, WOFF_W1 + l * 65536, gb1 + l * D2, geps + l, 0, D2, DD);
        else
            k_gemm_tc<3, false, true, false><<<dim3(D2 / 128, NN / 128), 256>>>(
                0, WOFF_W1 + l * 65536, gb1 + l * D2, geps + l, 0, D2, DD);
        k_bnfinal<<<1, D2>>>(gbng + l * D2, gbnb + l * D2);
        k_gemm_tc<2, false, true, false><<<dim3(DD / 128, NN / 128), 256>>>(
            0, WOFF_W2 + l * 65536, gb2 + l * DD, nullptr, 3, DD, D2);
        k_bnfinal2<<<1, DD>>>(bng + l * DD, bnb + l * DD);
    }
    k_bnapply<<<NN * DD / 4 / 256, 256>>>(out);
    k_final<<<1, 1>>>(out, (out_size > NN * DD) ? 1 : 0);
}

// round 15
// speedup vs baseline: 1.0126x; 1.0126x over previous
#include <cuda_runtime.h>
#include <cuda_bf16.h>
#include <math.h>

#define NN 65536
#define NE 262144
#define DD 256
#define D2 512
#define CHID 20

// pre-split weight buffer offsets (in words)
#define WOFF_WALL 0
#define WOFF_W1   16384
#define WOFF_W2   212992
#define WTOTAL    409600

// ------------------------- scratch (static device memory) -------------------
__device__ float g_x[NN * DD];
__device__ float g_h[NN * DD];          // z2 / h carrier between layers
__device__ float g_z1[NN * D2];
__device__ float g_agg[NN * DD];
__device__ float g_kappa[NN];
__device__ float g_f[3 * NN];
__device__ float g_fnacc[12 * NN];
__device__ float g_weights[NE];
__device__ float g_ew[NE];
__device__ float g_Wall[DD * 128];
__device__ float g_ball[128];
__device__ float4 g_W2p[128];           // packed second-layer heads (kappa,f0,f1,f2)
__device__ float g_b2p[4];
__device__ float g_h1raw[64];
__device__ float g_bnsum[D2];
__device__ float g_bnsq[D2];
__device__ float g_scale[D2];           // z1 BN
__device__ float g_bias[D2];
__device__ float g_scale2[DD];          // z2 BN
__device__ float g_bias2[DD];
__device__ float g_kapsum;
__device__ float g_loss;
__device__ unsigned g_hist[256];
__device__ unsigned g_prefix;
__device__ int g_rank;
__device__ int g_deg[NN];
__device__ int g_off[NN + 1];
__device__ int g_cur[NN];
__device__ int g_csr[NE];
__device__ __align__(16) unsigned g_Bh[WTOTAL];
__device__ __align__(16) unsigned g_Bl[WTOTAL];

__device__ __forceinline__ float sigmoidf_(float v) { return 1.0f / (1.0f + expf(-v)); }

// split-bf16 via packed cvt: hi/lo bf16x2 words for two adjacent-k fp32 values.
// Exact unpack: bf16 -> f32 is a left shift. ~6 ALU ops per 2 elements.
__device__ __forceinline__ void split2(float x, float y, unsigned &hi, unsigned &lo) {
    unsigned h;
    asm("cvt.rn.bf16x2.f32 %0, %1, %2;" : "=r"(h) : "f"(y), "f"(x));
    float hx = __uint_as_float(h << 16);
    float hy = __uint_as_float(h & 0xffff0000u);
    float lx = x - hx;
    float ly = y - hy;
    unsigned l;
    asm("cvt.rn.bf16x2.f32 %0, %1, %2;" : "=r"(l) : "f"(ly), "f"(lx));
    hi = h; lo = l;
}
__device__ __forceinline__ void mma16(float* c, const unsigned* a, const unsigned* b) {
    asm volatile("mma.sync.aligned.m16n8k16.row.col.f32.bf16.bf16.f32 "
        "{%0,%1,%2,%3}, {%4,%5,%6,%7}, {%8,%9}, {%0,%1,%2,%3};"
        : "+f"(c[0]), "+f"(c[1]), "+f"(c[2]), "+f"(c[3])
        : "r"(a[0]), "r"(a[1]), "r"(a[2]), "r"(a[3]), "r"(b[0]), "r"(b[1]));
}
__device__ __forceinline__ void cp16(void* s, const void* g) {
    unsigned saddr = (unsigned)__cvta_generic_to_shared(s);
    asm volatile("cp.async.cg.shared.global [%0], [%1], 16;\n" :: "r"(saddr), "l"(g));
}

// ------------------------------- init kernel --------------------------------
__global__ void k_zero_init() {
    int b = blockIdx.x, t = threadIdx.x;
    if (b < 256) {
        g_deg[b * 256 + t] = 0;
    } else {
        if (t < 64) g_h1raw[t] = 0.f;
        g_hist[t] = 0;
        g_bnsum[t] = 0.f; g_bnsq[t] = 0.f;
        g_bnsum[t + 256] = 0.f; g_bnsq[t + 256] = 0.f;
    }
}
__global__ void k_zero_fnacc() {
    int i = blockIdx.x * blockDim.x + threadIdx.x;
    for (; i < 12 * NN; i += gridDim.x * blockDim.x) g_fnacc[i] = 0.f;
}

// ------------------------------- CSR build ----------------------------------
__global__ void k_deg(const int* __restrict__ ei) {
    int e = blockIdx.x * blockDim.x + threadIdx.x;
    atomicAdd(&g_deg[ei[NE + e]], 1);
}
__global__ void k_scan() {
    __shared__ int part[1024];
    int t = threadIdx.x;
    int base = t * 64;
    int s = 0;
#pragma unroll 8
    for (int i = 0; i < 64; i++) s += g_deg[base + i];
    part[t] = s;
    __syncthreads();
    for (int d = 1; d < 1024; d <<= 1) {
        int v = (t >= d) ? part[t - d] : 0;
        __syncthreads();
        part[t] += v;
        __syncthreads();
    }
    int run = part[t] - s;
    for (int i = 0; i < 64; i++) {
        g_off[base + i] = run;
        g_cur[base + i] = run;
        run += g_deg[base + i];
    }
    if (t == 1023) g_off[NN] = run;
}
__global__ void k_fill(const int* __restrict__ ei) {
    int e = blockIdx.x * blockDim.x + threadIdx.x;
    int d = ei[NE + e];
    int pos = atomicAdd(&g_cur[d], 1);
    g_csr[pos] = e;
}

// ------------------------------- atom embedding -----------------------------
__global__ void k_embed(const int* __restrict__ xa, const float* __restrict__ emb) {
    int n = blockIdx.x * 8 + (threadIdx.x >> 5);
    int lane = threadIdx.x & 31;
    float4 a0 = make_float4(0.f, 0.f, 0.f, 0.f);
    float4 a1 = make_float4(0.f, 0.f, 0.f, 0.f);
#pragma unroll
    for (int f = 0; f < 9; f++) {
        int v = xa[n * 9 + f];
        const float4* row = (const float4*)(emb + ((size_t)(f * 128 + v)) * DD);
        float4 b0 = row[lane * 2], b1 = row[lane * 2 + 1];
        a0.x += b0.x; a0.y += b0.y; a0.z += b0.z; a0.w += b0.w;
        a1.x += b1.x; a1.y += b1.y; a1.z += b1.z; a1.w += b1.w;
    }
    float4* out = (float4*)(g_x + (size_t)n * DD);
    out[lane * 2] = a0; out[lane * 2 + 1] = a1;
}

// ------- pack the 4 small-MLP first layers into [256,128] + head pack -------
__global__ void k_packW(const float* __restrict__ cw1, const float* __restrict__ cb1,
                        const float* __restrict__ fw1, const float* __restrict__ fb1,
                        const float* __restrict__ cw2, const float* __restrict__ cb2,
                        const float* __restrict__ fw2, const float* __restrict__ fb2) {
    int idx = blockIdx.x * blockDim.x + threadIdx.x;
    if (idx >= DD * 128) return;
    int k = idx >> 7, u = idx & 127;
    float v = 0.f;
    if (u < CHID) v = cw1[k * CHID + u];
    else if (u < 80) {
        int i = (u - CHID) / CHID, j = (u - CHID) % CHID;
        v = fw1[((size_t)i * DD + k) * CHID + j];
    }
    g_Wall[idx] = v;
    if (k == 0) {
        float b = 0.f;
        if (u < CHID) b = cb1[u];
        else if (u < 80) { int i = (u - CHID) / CHID, j = (u - CHID) % CHID; b = fb1[i * CHID + j]; }
        g_ball[u] = b;
        float4 wp = make_float4(0.f, 0.f, 0.f, 0.f);
        if (u < 20) wp.x = cw2[u];
        else if (u < 40) wp.y = fw2[0 * CHID + (u - 20)];
        else if (u < 60) wp.z = fw2[1 * CHID + (u - 40)];
        else if (u < 80) wp.w = fw2[2 * CHID + (u - 60)];
        g_W2p[u] = wp;
        if (u == 0) {
            g_b2p[0] = cb2[0];
            g_b2p[1] = fb2[0]; g_b2p[2] = fb2[1]; g_b2p[3] = fb2[2];
            g_kapsum = 0.f; g_loss = 0.f;
        }
    }
}

// ------ pre-split ALL weight matrices into swizzled bf16 hi/lo layout -------
__global__ void k_presplit_all(const float* __restrict__ gw1, const float* __restrict__ gw2) {
    int id = blockIdx.x * blockDim.x + threadIdx.x;
    if (id >= WTOTAL) return;
    const float* src;
    int K, Nc, rem;
    if (id < WOFF_W1) {
        src = g_Wall; K = 256; Nc = 128; rem = id;
    } else if (id < WOFF_W2) {
        int rid = id - WOFF_W1;
        int l = rid >> 16; rem = rid & 65535;
        src = gw1 + (size_t)l * (DD * D2); K = 256; Nc = 512;
    } else {
        int rid = id - WOFF_W2;
        int l = rid >> 16; rem = rid & 65535;
        src = gw2 + (size_t)l * (D2 * DD); K = 512; Nc = 256;
    }
    int kw = K >> 1;
    int n = rem / kw, r2 = rem - n * kw;
    int kt = r2 >> 3, c = r2 & 7;
    int p = ((c & 1) << 2) | (((c >> 1) ^ n) & 3);
    int k0 = kt * 16 + 2 * p;
    unsigned hi, lo;
    split2(src[(size_t)k0 * Nc + n], src[(size_t)(k0 + 1) * Nc + n], hi, lo);
    g_Bh[id] = hi;
    g_Bl[id] = lo;
}

// ------------- split-bf16 (3-term, ~fp32) tensor-core GEMM ------------------
// AMODE 0: A=g_x (MLP);  1: alpha*g_x+g_agg;  2: relu(z1*sc+bb);
// AMODE 3: alpha*relu(g_h*sc2+bb2)+g_agg
template <int AMODE>
__device__ __forceinline__ float4 loadA_t(const float* __restrict__ A, size_t rowoff,
                                          int col, float alpha) {
    float4 va = *(const float4*)(A + rowoff + col);
    if (AMODE == 1) {
        float4 w = *(const float4*)(g_agg + rowoff + col);
        va.x = alpha * va.x + w.x; va.y = alpha * va.y + w.y;
        va.z = alpha * va.z + w.z; va.w = alpha * va.w + w.w;
    }
    if (AMODE == 2) {
        float4 sc = *(const float4*)(g_scale + col);
        float4 bb = *(const float4*)(g_bias + col);
        va.x = fmaxf(va.x * sc.x + bb.x, 0.f);
        va.y = fmaxf(va.y * sc.y + bb.y, 0.f);
        va.z = fmaxf(va.z * sc.z + bb.z, 0.f);
        va.w = fmaxf(va.w * sc.w + bb.w, 0.f);
    }
    if (AMODE == 3) {
        float4 sc = *(const float4*)(g_scale2 + col);
        float4 bb = *(const float4*)(g_bias2 + col);
        float4 w = *(const float4*)(g_agg + rowoff + col);
        va.x = alpha * fmaxf(va.x * sc.x + bb.x, 0.f) + w.x;
        va.y = alpha * fmaxf(va.y * sc.y + bb.y, 0.f) + w.y;
        va.z = alpha * fmaxf(va.z * sc.z + bb.z, 0.f) + w.z;
        va.w = alpha * fmaxf(va.w * sc.w + bb.w, 0.f) + w.w;
    }
    return va;
}

template <int AMODE, bool RELU, bool STATS, bool MLPEPI>
__global__ __launch_bounds__(256, 2) void k_gemm_tc(int Asel,
        int Boff, const float* __restrict__ biasp,
        const float* __restrict__ epsp, int Csel, int Nc, int K) {
    __shared__ unsigned Ahs[2][128][8], Als[2][128][8];
    __shared__ unsigned Bhs[2][128][8], Bls[2][128][8];
    __shared__ float sredS[128], sredQ[128];

    const float* A;
    if (AMODE == 0) A = g_x;
    else if (AMODE == 1) A = (Asel == 0) ? g_x : g_h;
    else if (AMODE == 3) A = g_h;
    else A = g_z1;
    const float* bias = (AMODE == 0) ? g_ball : biasp;
    float* C = (Csel == 0) ? g_z1 : ((Csel == 1) ? g_agg : g_h);
    float alpha = (AMODE == 1 || AMODE == 3) ? (1.0f + epsp[0]) : 0.f;

    int tid = threadIdx.x;
    int bm = blockIdx.y * 128, bn = blockIdx.x * 128;
    if (STATS && tid < 128) { sredS[tid] = 0.f; sredQ[tid] = 0.f; }

    int aRow = tid >> 2, aP0 = (tid & 3) * 2;
    int aCol0 = aP0 * 2;
    int r3f = aRow & 3;
    int cA0 = 2 * ((aP0 & 3) ^ r3f) + (aP0 >> 2);
    int cA1 = 2 * (((aP0 + 1) & 3) ^ r3f) + ((aP0 + 1) >> 2);
    size_t aoff0 = (size_t)(bm + aRow) * K;
    size_t aoff1 = (size_t)(bm + aRow + 64) * K;
    int nl = tid >> 1, halfB = (tid & 1) * 4;
    const unsigned* bhsrc = g_Bh + Boff + (size_t)(bn + nl) * (K >> 1) + halfB;
    const unsigned* blsrc = g_Bl + Boff + (size_t)(bn + nl) * (K >> 1) + halfB;

    int w = tid >> 5, lane = tid & 31;
    int wm = (w >> 1) * 32, wn = (w & 1) * 64;
    int qr = lane >> 2, qc = lane & 3;
    int j2 = 2 * (qc ^ (qr & 3));

    float acc[2][8][4];
#pragma unroll
    for (int mt = 0; mt < 2; mt++)
#pragma unroll
        for (int nt = 0; nt < 8; nt++)
#pragma unroll
            for (int j = 0; j < 4; j++) acc[mt][nt][j] = 0.f;

    float4 va0, va1;
    unsigned th, tl;

    cp16(&Bhs[0][nl][halfB], bhsrc);
    cp16(&Bls[0][nl][halfB], blsrc);
    asm volatile("cp.async.commit_group;\n");
    va0 = loadA_t<AMODE>(A, aoff0, aCol0, alpha);
    va1 = loadA_t<AMODE>(A, aoff1, aCol0, alpha);
    split2(va0.x, va0.y, th, tl); Ahs[0][aRow][cA0] = th; Als[0][aRow][cA0] = tl;
    split2(va0.z, va0.w, th, tl); Ahs[0][aRow][cA1] = th; Als[0][aRow][cA1] = tl;
    split2(va1.x, va1.y, th, tl); Ahs[0][aRow + 64][cA0] = th; Als[0][aRow + 64][cA0] = tl;
    split2(va1.z, va1.w, th, tl); Ahs[0][aRow + 64][cA1] = th; Als[0][aRow + 64][cA1] = tl;
    asm volatile("cp.async.wait_group 0;\n");
    __syncthreads();

    int buf = 0;
#pragma unroll 1
    for (int k0 = 0; k0 < K; k0 += 16) {
        int kn = k0 + 16;
        if (kn < K) {
            cp16(&Bhs[buf ^ 1][nl][halfB], bhsrc + (kn >> 1));
            cp16(&Bls[buf ^ 1][nl][halfB], blsrc + (kn >> 1));
            asm volatile("cp.async.commit_group;\n");
            va0 = loadA_t<AMODE>(A, aoff0, kn + aCol0, alpha);
            va1 = loadA_t<AMODE>(A, aoff1, kn + aCol0, alpha);
        }
        unsigned ah[2][4], al_[2][4];
#pragma unroll
        for (int mt = 0; mt < 2; mt++) {
            int r = wm + mt * 16 + qr;
            uint2 x0 = *(const uint2*)&Ahs[buf][r][j2];
            uint2 x1 = *(const uint2*)&Ahs[buf][r + 8][j2];
            ah[mt][0] = x0.x; ah[mt][1] = x1.x; ah[mt][2] = x0.y; ah[mt][3] = x1.y;
            uint2 y0 = *(const uint2*)&Als[buf][r][j2];
            uint2 y1 = *(const uint2*)&Als[buf][r + 8][j2];
            al_[mt][0] = y0.x; al_[mt][1] = y1.x; al_[mt][2] = y0.y; al_[mt][3] = y1.y;
        }
#pragma unroll
        for (int nt = 0; nt < 8; nt++) {
            int n = wn + nt * 8 + qr;
            uint2 bh2 = *(const uint2*)&Bhs[buf][n][j2];
            uint2 bl2 = *(const uint2*)&Bls[buf][n][j2];
            unsigned bhf[2] = {bh2.x, bh2.y};
            unsigned blf[2] = {bl2.x, bl2.y};
            mma16(acc[0][nt], ah[0], bhf);
            mma16(acc[1][nt], ah[1], bhf);
            mma16(acc[0][nt], ah[0], blf);
            mma16(acc[1][nt], ah[1], blf);
            mma16(acc[0][nt], al_[0], bhf);
            mma16(acc[1][nt], al_[1], bhf);
        }
        if (kn < K) {
            int nb = buf ^ 1;
            split2(va0.x, va0.y, th, tl); Ahs[nb][aRow][cA0] = th; Als[nb][aRow][cA0] = tl;
            split2(va0.z, va0.w, th, tl); Ahs[nb][aRow][cA1] = th; Als[nb][aRow][cA1] = tl;
            split2(va1.x, va1.y, th, tl); Ahs[nb][aRow + 64][cA0] = th; Als[nb][aRow + 64][cA0] = tl;
            split2(va1.z, va1.w, th, tl); Ahs[nb][aRow + 64][cA1] = th; Als[nb][aRow + 64][cA1] = tl;
            asm volatile("cp.async.wait_group 0;\n");
            __syncthreads();
            buf ^= 1;
        }
    }

    float psum[16], psq[16];
    if (STATS) {
#pragma unroll
        for (int j = 0; j < 16; j++) { psum[j] = 0.f; psq[j] = 0.f; }
    }
    float racc[4][4];
    if (MLPEPI) {
#pragma unroll
        for (int s = 0; s < 4; s++)
#pragma unroll
            for (int o = 0; o < 4; o++) racc[s][o] = 0.f;
    }
#pragma unroll
    for (int nt = 0; nt < 8; nt++) {
        int cc0 = wn + nt * 8 + qc * 2;
        int col0 = bn + cc0;
        float bv0 = bias[col0], bv1 = bias[col0 + 1];
#pragma unroll
        for (int mt = 0; mt < 2; mt++) {
            int row0 = bm + wm + mt * 16 + qr;
            float v00 = acc[mt][nt][0] + bv0;
            float v01 = acc[mt][nt][1] + bv1;
            float v10 = acc[mt][nt][2] + bv0;
            float v11 = acc[mt][nt][3] + bv1;
            if (RELU) {
                v00 = fmaxf(v00, 0.f); v01 = fmaxf(v01, 0.f);
                v10 = fmaxf(v10, 0.f); v11 = fmaxf(v11, 0.f);
            }
            if (STATS) {
                psum[nt * 2 + 0] += v00 + v10;
                psum[nt * 2 + 1] += v01 + v11;
                psq[nt * 2 + 0] += v00 * v00 + v10 * v10;
                psq[nt * 2 + 1] += v01 * v01 + v11 * v11;
            }
            if (MLPEPI) {
                float4 w0 = g_W2p[cc0], w1 = g_W2p[cc0 + 1];
                racc[mt * 2 + 0][0] += v00 * w0.x + v01 * w1.x;
                racc[mt * 2 + 0][1] += v00 * w0.y + v01 * w1.y;
                racc[mt * 2 + 0][2] += v00 * w0.z + v01 * w1.z;
                racc[mt * 2 + 0][3] += v00 * w0.w + v01 * w1.w;
                racc[mt * 2 + 1][0] += v10 * w0.x + v11 * w1.x;
                racc[mt * 2 + 1][1] += v10 * w0.y + v11 * w1.y;
                racc[mt * 2 + 1][2] += v10 * w0.z + v11 * w1.z;
                racc[mt * 2 + 1][3] += v10 * w0.w + v11 * w1.w;
            } else {
                *(float2*)(C + (size_t)row0 * Nc + col0) = make_float2(v00, v01);
                *(float2*)(C + (size_t)(row0 + 8) * Nc + col0) = make_float2(v10, v11);
            }
        }
    }
    if (MLPEPI) {
#pragma unroll
        for (int s = 0; s < 4; s++)
#pragma unroll
            for (int o = 0; o < 4; o++) {
                racc[s][o] += __shfl_xor_sync(0xffffffff, racc[s][o], 1);
                racc[s][o] += __shfl_xor_sync(0xffffffff, racc[s][o], 2);
            }
        __syncthreads();
        float* sred = (float*)&Ahs[0][0][0];
        if ((lane & 3) == 0) {
#pragma unroll
            for (int s = 0; s < 4; s++) {
                int row = wm + (s >> 1) * 16 + qr + (s & 1) * 8;
#pragma unroll
                for (int o = 0; o < 4; o++)
                    sred[row * 8 + (w & 1) * 4 + o] = racc[s][o];
            }
        }
        __syncthreads();
        if (tid < 128) {
            float o0 = sred[tid * 8 + 0] + sred[tid * 8 + 4] + g_b2p[0];
            float o1 = sred[tid * 8 + 1] + sred[tid * 8 + 5] + g_b2p[1];
            float o2 = sred[tid * 8 + 2] + sred[tid * 8 + 6] + g_b2p[2];
            float o3 = sred[tid * 8 + 3] + sred[tid * 8 + 7] + g_b2p[3];
            int row = bm + tid;
            float kap = sigmoidf_(o0);
            g_kappa[row] = kap;
            g_f[row] = sigmoidf_(o1);
            g_f[NN + row] = sigmoidf_(o2);
            g_f[2 * NN + row] = sigmoidf_(o3);
            float kp = kap;
#pragma unroll
            for (int off = 16; off > 0; off >>= 1)
                kp += __shfl_xor_sync(0xffffffff, kp, off);
            if (lane == 0) atomicAdd(&g_kapsum, kp);
        }
    }
    if (STATS) {
#pragma unroll
        for (int j = 0; j < 16; j++) {
#pragma unroll
            for (int off = 4; off < 32; off <<= 1) {
                psum[j] += __shfl_xor_sync(0xffffffff, psum[j], off);
                psq[j] += __shfl_xor_sync(0xffffffff, psq[j], off);
            }
        }
        if (lane < 4) {
#pragma unroll
            for (int nt = 0; nt < 8; nt++) {
#pragma unroll
                for (int h = 0; h < 2; h++) {
                    int cl = wn + nt * 8 + lane * 2 + h;
                    atomicAdd(&sredS[cl], psum[nt * 2 + h]);
                    atomicAdd(&sredQ[cl], psq[nt * 2 + h]);
                }
            }
        }
        __syncthreads();
        if (tid < 128) {
            atomicAdd(&g_bnsum[bn + tid], sredS[tid]);
            atomicAdd(&g_bnsq[bn + tid], sredQ[tid]);
        }
    }
}

// ------------------------------- WeightMLP ----------------------------------
__global__ void k_wm_reduce(const int* __restrict__ ea, const float* __restrict__ w1) {
    __shared__ float sm[4][64];
    int t = threadIdx.x, g = t >> 6, j = t & 63;
    float acc = 0.f;
    for (int e = blockIdx.x * 4 + g; e < NE; e += gridDim.x * 4) {
        float s = (float)(ea[e * 3] + ea[e * 3 + 1] + ea[e * 3 + 2]);
        acc += s * w1[(size_t)e * 64 + j];
    }
    sm[g][j] = acc;
    __syncthreads();
    if (g == 0) atomicAdd(&g_h1raw[j], sm[0][j] + sm[1][j] + sm[2][j] + sm[3][j]);
}
__global__ void k_weights(const float* __restrict__ b1, const float* __restrict__ w2,
                          const float* __restrict__ b2, const float* __restrict__ w3,
                          const float* __restrict__ b3) {
    __shared__ float h1[64], h2[64];
    int t = threadIdx.x;
    if (t < 64) h1[t] = fmaxf(g_h1raw[t] + b1[t], 0.f);
    __syncthreads();
    if (t < 64) {
        float a = b2[t];
#pragma unroll 8
        for (int k = 0; k < 64; k++) a += h1[k] * w2[k * 64 + t];
        h2[t] = fmaxf(a, 0.f);
    }
    __syncthreads();
    int e = blockIdx.x * 256 + t;
    float acc = b3[e];
#pragma unroll 8
    for (int k = 0; k < 64; k++) acc += h2[k] * w3[(size_t)k * NE + e];
    g_weights[e] = sigmoidf_(acc);
}

// -------------------- exact top-k threshold (parallel radix) ----------------
__global__ void k_rinit(const int* __restrict__ pp) {
    long long nr = (long long)NN * (long long)pp[0] / 100;
    int r = (int)((nr < 100) ? nr : 100);
    if (r < 1) r = 1;
    g_rank = r;
    g_prefix = 0;
}
__global__ void k_hist(int pass) {
    __shared__ unsigned sh[256];
    int t = threadIdx.x;
    sh[t] = 0;
    __syncthreads();
    int shift = 24 - pass * 8;
    unsigned pfx = g_prefix;
    for (int i = blockIdx.x * 256 + t; i < NN; i += gridDim.x * 256) {
        unsigned bits = __float_as_uint(g_kappa[i]);
        bool ok = (pass == 0) || ((bits >> (shift + 8)) == (pfx >> (shift + 8)));
        if (ok) atomicAdd(&sh[(bits >> shift) & 255], 1u);
    }
    __syncthreads();
    if (sh[t]) atomicAdd(&g_hist[t], sh[t]);
}
__global__ void k_rsel(int pass) {
    __shared__ unsigned h[256];
    int t = threadIdx.x;
    h[t] = g_hist[t];
    g_hist[t] = 0;
    __syncthreads();
    if (t == 0) {
        int r = g_rank;
        unsigned d = 255;
        for (;; d--) {
            unsigned c = h[d];
            if (r <= (int)c || d == 0) break;
            r -= (int)c;
        }
        g_rank = r;
        g_prefix |= (d << (24 - pass * 8));
    }
}
__global__ void k_ew(const int* __restrict__ ei) {
    int e = blockIdx.x * blockDim.x + threadIdx.x;
    unsigned thr = g_prefix;
    unsigned a = __float_as_uint(g_kappa[ei[e]]);
    unsigned b = __float_as_uint(g_kappa[ei[NE + e]]);
    g_ew[e] = (a >= thr || b >= thr) ? 1e-5f : 1.0f;
}

// ----------------------- Bakry-Emery functional passes ----------------------
__global__ void k_fnA(const int* __restrict__ ei) {
    int e = blockIdx.x * blockDim.x + threadIdx.x;
    int s = ei[e], d = ei[NE + e];
    float w = g_weights[e];
#pragma unroll
    for (int i = 0; i < 3; i++) {
        float fd = g_f[i * NN + d] - g_f[i * NN + s];
        atomicAdd(&g_fnacc[i * NN + s], 0.5f * w * fd * fd);
        atomicAdd(&g_fnacc[3 * NN + i * NN + s], w * fd);
    }
}
__global__ void k_fnB(const int* __restrict__ ei) {
    int e = blockIdx.x * blockDim.x + threadIdx.x;
    int s = ei[e], d = ei[NE + e];
    float w = g_weights[e];
#pragma unroll
    for (int i = 0; i < 3; i++) {
        float gd = g_fnacc[i * NN + d] - g_fnacc[i * NN + s];
        atomicAdd(&g_fnacc[6 * NN + i * NN + s], w * gd);
        float fd = g_f[i * NN + d] - g_f[i * NN + s];
        float dfd = g_fnacc[3 * NN + i * NN + d] - g_fnacc[3 * NN + i * NN + s];
        atomicAdd(&g_fnacc[9 * NN + i * NN + s], 0.5f * w * fd * dfd);
    }
}
__global__ void k_fnC() {
    __shared__ float red[256];
    int n = blockIdx.x * 256 + threadIdx.x;
    float kap = g_kappa[n];
    float part = 0.f;
#pragma unroll
    for (int i = 0; i < 3; i++) {
        float gam = g_fnacc[i * NN + n];
        float dg = g_fnacc[6 * NN + i * NN + n];
        float gfd = g_fnacc[9 * NN + i * NN + n];
        part += fmaxf(kap * gam - (0.5f * dg - gfd), 0.f);
    }
    red[threadIdx.x] = part;
    __syncthreads();
    for (int s = 128; s > 0; s >>= 1) { if (threadIdx.x < s) red[threadIdx.x] += red[threadIdx.x + s]; __syncthreads(); }
    if (threadIdx.x == 0) atomicAdd(&g_loss, red[0]);
}

// ------- GIN message: CSR gather; HSEL=1 applies h=relu(BN2(z2)) on read ----
template <int HSEL>
__global__ void k_msg2(const int* __restrict__ ei, const int* __restrict__ ea,
                       const float* __restrict__ bemb) {
    const float* h = HSEL ? g_h : g_x;
    int n = blockIdx.x * 8 + (threadIdx.x >> 5);
    int lane = threadIdx.x & 31;
    int beg = g_off[n], end = g_off[n + 1];
    float4 a0 = make_float4(0.f, 0.f, 0.f, 0.f);
    float4 a1 = make_float4(0.f, 0.f, 0.f, 0.f);
    int q = lane * 2;
    float4 sc0, bb0, sc1, bb1;
    if (HSEL) {
        sc0 = ((const float4*)g_scale2)[q];     bb0 = ((const float4*)g_bias2)[q];
        sc1 = ((const float4*)g_scale2)[q + 1]; bb1 = ((const float4*)g_bias2)[q + 1];
    }
    for (int p = beg; p < end; p++) {
        int e = g_csr[p];
        int s = ei[e];
        float w = g_ew[e];
        const float4* b0 = (const float4*)(bemb + (size_t)(0 * 8 + ea[e * 3 + 0]) * DD);
        const float4* b1 = (const float4*)(bemb + (size_t)(1 * 8 + ea[e * 3 + 1]) * DD);
        const float4* b2 = (const float4*)(bemb + (size_t)(2 * 8 + ea[e * 3 + 2]) * DD);
        const float4* hs = (const float4*)(h + (size_t)s * DD);
        float4 v = hs[q];
        if (HSEL) {
            v.x = fmaxf(v.x * sc0.x + bb0.x, 0.f);
            v.y = fmaxf(v.y * sc0.y + bb0.y, 0.f);
            v.z = fmaxf(v.z * sc0.z + bb0.z, 0.f);
            v.w = fmaxf(v.w * sc0.w + bb0.w, 0.f);
        }
        float4 x0 = b0[q], x1 = b1[q], x2 = b2[q];
        a0.x += fmaxf(v.x + x0.x + x1.x + x2.x, 0.f) * w;
        a0.y += fmaxf(v.y + x0.y + x1.y + x2.y, 0.f) * w;
        a0.z += fmaxf(v.z + x0.z + x1.z + x2.z, 0.f) * w;
        a0.w += fmaxf(v.w + x0.w + x1.w + x2.w, 0.f) * w;
        v = hs[q + 1];
        if (HSEL) {
            v.x = fmaxf(v.x * sc1.x + bb1.x, 0.f);
            v.y = fmaxf(v.y * sc1.y + bb1.y, 0.f);
            v.z = fmaxf(v.z * sc1.z + bb1.z, 0.f);
            v.w = fmaxf(v.w * sc1.w + bb1.w, 0.f);
        }
        x0 = b0[q + 1]; x1 = b1[q + 1]; x2 = b2[q + 1];
        a1.x += fmaxf(v.x + x0.x + x1.x + x2.x, 0.f) * w;
        a1.y += fmaxf(v.y + x0.y + x1.y + x2.y, 0.f) * w;
        a1.z += fmaxf(v.z + x0.z + x1.z + x2.z, 0.f) * w;
        a1.w += fmaxf(v.w + x0.w + x1.w + x2.w, 0.f) * w;
    }
    float4* out = (float4*)(g_agg + (size_t)n * DD);
    out[q] = a0; out[q + 1] = a1;
}

// ----------------------------- BN final + apply -----------------------------
__global__ void k_bnfinal(const float* __restrict__ g, const float* __restrict__ b) {
    int c = threadIdx.x;
    float mean = g_bnsum[c] * (1.0f / NN);
    float var = g_bnsq[c] * (1.0f / NN) - mean * mean;
    float inv = rsqrtf(var + 1e-5f);
    float sc = g[c] * inv;
    g_scale[c] = sc;
    g_bias[c] = b[c] - mean * sc;
    g_bnsum[c] = 0.f;
    g_bnsq[c] = 0.f;
}
__global__ void k_bnfinal2(const float* __restrict__ g, const float* __restrict__ b) {
    int c = threadIdx.x;
    float mean = g_bnsum[c] * (1.0f / NN);
    float var = g_bnsq[c] * (1.0f / NN) - mean * mean;
    float inv = rsqrtf(var + 1e-5f);
    float sc = g[c] * inv;
    g_scale2[c] = sc;
    g_bias2[c] = b[c] - mean * sc;
    g_bnsum[c] = 0.f;
    g_bnsq[c] = 0.f;
}
__global__ void k_bnapply(float* __restrict__ dout) {
    int i = blockIdx.x * blockDim.x + threadIdx.x;
    float4 v = ((const float4*)g_h)[i];
    int cb = i & (DD / 4 - 1);
    float4 sc = ((const float4*)g_scale2)[cb];
    float4 bb = ((const float4*)g_bias2)[cb];
    v.x = v.x * sc.x + bb.x; v.y = v.y * sc.y + bb.y;
    v.z = v.z * sc.z + bb.z; v.w = v.w * sc.w + bb.w;
    ((float4*)dout)[i] = v;
}
__global__ void k_final(float* __restrict__ dout, int write) {
    if (write) dout[(size_t)NN * DD] = g_loss - 3.0f * g_kapsum;
}

// --------------------------------- launcher ---------------------------------
extern "C" void kernel_launch(void* const* d_in, const int* in_sizes, int n_in,
                              void* d_out, int out_size) {
    const int*   xa   = (const int*)d_in[0];
    const int*   ei   = (const int*)d_in[1];
    const int*   ea   = (const int*)d_in[2];
    const int*   pp   = (const int*)d_in[3];
    const float* aemb = (const float*)d_in[4];
    const float* bemb = (const float*)d_in[5];
    const float* gw1  = (const float*)d_in[6];
    const float* gb1  = (const float*)d_in[7];
    const float* gbng = (const float*)d_in[8];
    const float* gbnb = (const float*)d_in[9];
    const float* gw2  = (const float*)d_in[10];
    const float* gb2  = (const float*)d_in[11];
    const float* geps = (const float*)d_in[12];
    const float* bng  = (const float*)d_in[13];
    const float* bnb  = (const float*)d_in[14];
    const float* cw1  = (const float*)d_in[15];
    const float* cb1  = (const float*)d_in[16];
    const float* cw2  = (const float*)d_in[17];
    const float* cb2  = (const float*)d_in[18];
    const float* fw1  = (const float*)d_in[19];
    const float* fb1  = (const float*)d_in[20];
    const float* fw2  = (const float*)d_in[21];
    const float* fb2  = (const float*)d_in[22];
    const float* wmw1 = (const float*)d_in[23];
    const float* wmb1 = (const float*)d_in[24];
    const float* wmw2 = (const float*)d_in[25];
    const float* wmb2 = (const float*)d_in[26];
    const float* wmw3 = (const float*)d_in[27];
    const float* wmb3 = (const float*)d_in[28];
    float* out = (float*)d_out;

    // launches 1-3, then #4 = MLP GEMM (ncu captures launch #4)
    k_packW<<<(DD * 128 + 255) / 256, 256>>>(cw1, cb1, fw1, fb1, cw2, cb2, fw2, fb2);
    k_presplit_all<<<(WTOTAL + 255) / 256, 256>>>(gw1, gw2);
    k_embed<<<NN / 8, 256>>>(xa, aemb);
    k_gemm_tc<0, true, false, true><<<dim3(1, NN / 128), 256>>>(0, WOFF_WALL, nullptr, nullptr, 0, 128, DD);

    k_zero_init<<<257, 256>>>();
    k_deg<<<NE / 256, 256>>>(ei);
    k_scan<<<1, 1024>>>();
    k_fill<<<NE / 256, 256>>>(ei);
    k_wm_reduce<<<512, 256>>>(ea, wmw1);
    k_weights<<<NE / 256, 256>>>(wmb1, wmw2, wmb2, wmw3, wmb3);
    k_rinit<<<1, 1>>>(pp);
    for (int p = 0; p < 4; p++) {
        k_hist<<<64, 256>>>(p);
        k_rsel<<<1, 256>>>(p);
    }
    k_ew<<<NE / 256, 256>>>(ei);
    k_zero_fnacc<<<768, 256>>>();
    k_fnA<<<NE / 256, 256>>>(ei);
    k_fnB<<<NE / 256, 256>>>(ei);
    k_fnC<<<NN / 256, 256>>>();

    for (int l = 0; l < 3; l++) {
        if (l == 0)
            k_msg2<0><<<NN / 8, 256>>>(ei, ea, bemb + (size_t)l * 3 * 8 * DD);
        else
            k_msg2<1><<<NN / 8, 256>>>(ei, ea, bemb + (size_t)l * 3 * 8 * DD);
        if (l == 0)
            k_gemm_tc<1, false, true, false><<<dim3(D2 / 128, NN / 128), 256>>>(
                0, WOFF_W1 + l * 65536, gb1 + l * D2, geps + l, 0, D2, DD);
        else
            k_gemm_tc<3, false, true, false><<<dim3(D2 / 128, NN / 128), 256>>>(
                0, WOFF_W1 + l * 65536, gb1 + l * D2, geps + l, 0, D2, DD);
        k_bnfinal<<<1, D2>>>(gbng + l * D2, gbnb + l * D2);
        k_gemm_tc<2, false, true, false><<<dim3(DD / 128, NN / 128), 256>>>(
            0, WOFF_W2 + l * 65536, gb2 + l * DD, nullptr, 3, DD, D2);
        k_bnfinal2<<<1, DD>>>(bng + l * DD, bnb + l * DD);
    }
    k_bnapply<<<NN * DD / 4 / 256, 256>>>(out);
    k_final<<<1, 1>>>(out, (out_size > NN * DD) ? 1 : 0);
}

// round 16
// speedup vs baseline: 1.0634x; 1.0502x over previous
#include <cuda_runtime.h>
#include <cuda_bf16.h>
#include <math.h>

#define NN 65536
#define NE 262144
#define DD 256
#define D2 512
#define CHID 20

// pre-split weight buffer offsets (in words)
#define WOFF_WALL 0
#define WOFF_W1   16384
#define WOFF_W2   212992
#define WTOTAL    409600

#define DSMSZ (12 * 1024 * 4)   // 3-stage x 4 arrays x 4KB

// ------------------------- scratch (static device memory) -------------------
__device__ float g_x[NN * DD];
__device__ float g_h[NN * DD];          // z2 / h carrier between layers
__device__ float g_z1[NN * D2];
__device__ float g_kappa[NN];
__device__ float g_f[3 * NN];
__device__ float g_fnacc[12 * NN];
__device__ float g_weights[NE];
__device__ float g_ew[NE];
__device__ float g_Wall[DD * 128];
__device__ float g_ball[128];
__device__ float4 g_W2p[128];
__device__ float g_b2p[4];
__device__ float g_h1raw[64];
__device__ float g_bnsum[D2];
__device__ float g_bnsq[D2];
__device__ float g_scale[D2];           // z1 BN
__device__ float g_bias[D2];
__device__ float g_scale2[DD];          // z2 BN
__device__ float g_bias2[DD];
__device__ float g_kapsum;
__device__ float g_loss;
__device__ unsigned g_hist[256];
__device__ unsigned g_prefix;
__device__ int g_rank;
__device__ int g_deg[NN];
__device__ int g_off[NN + 1];
__device__ int g_cur[NN];
__device__ int g_csr[NE];
__device__ __align__(16) unsigned g_Bh[WTOTAL];
__device__ __align__(16) unsigned g_Bl[WTOTAL];
__device__ __align__(16) unsigned g_Ah[NN * 128];   // split A (K=256)
__device__ __align__(16) unsigned g_Al[NN * 128];

__device__ __forceinline__ float sigmoidf_(float v) { return 1.0f / (1.0f + expf(-v)); }

// split-bf16 via packed cvt
__device__ __forceinline__ void split2(float x, float y, unsigned &hi, unsigned &lo) {
    unsigned h;
    asm("cvt.rn.bf16x2.f32 %0, %1, %2;" : "=r"(h) : "f"(y), "f"(x));
    float hx = __uint_as_float(h << 16);
    float hy = __uint_as_float(h & 0xffff0000u);
    float lx = x - hx;
    float ly = y - hy;
    unsigned l;
    asm("cvt.rn.bf16x2.f32 %0, %1, %2;" : "=r"(l) : "f"(ly), "f"(lx));
    hi = h; lo = l;
}
__device__ __forceinline__ void mma16(float* c, const unsigned* a, const unsigned* b) {
    asm volatile("mma.sync.aligned.m16n8k16.row.col.f32.bf16.bf16.f32 "
        "{%0,%1,%2,%3}, {%4,%5,%6,%7}, {%8,%9}, {%0,%1,%2,%3};"
        : "+f"(c[0]), "+f"(c[1]), "+f"(c[2]), "+f"(c[3])
        : "r"(a[0]), "r"(a[1]), "r"(a[2]), "r"(a[3]), "r"(b[0]), "r"(b[1]));
}
__device__ __forceinline__ void cp16(void* s, const void* g) {
    unsigned saddr = (unsigned)__cvta_generic_to_shared(s);
    asm volatile("cp.async.cg.shared.global [%0], [%1], 16;\n" :: "r"(saddr), "l"(g));
}

// write one node-row (8 floats per lane) as split-swizzled A
__device__ __forceinline__ void storeA_row(int n, int lane, float4 av0, float4 av1) {
    size_t base = (size_t)n * 128 + (lane >> 1) * 8;
    int bsel = lane & 1, m3 = n & 3;
    unsigned hi, lo;
    split2(av0.x, av0.y, hi, lo);
    int c = 2 * (0 ^ m3) + bsel; g_Ah[base + c] = hi; g_Al[base + c] = lo;
    split2(av0.z, av0.w, hi, lo);
    c = 2 * (1 ^ m3) + bsel; g_Ah[base + c] = hi; g_Al[base + c] = lo;
    split2(av1.x, av1.y, hi, lo);
    c = 2 * (2 ^ m3) + bsel; g_Ah[base + c] = hi; g_Al[base + c] = lo;
    split2(av1.z, av1.w, hi, lo);
    c = 2 * (3 ^ m3) + bsel; g_Ah[base + c] = hi; g_Al[base + c] = lo;
}

// ------------------------------- init kernel --------------------------------
__global__ void k_zero_init() {
    int b = blockIdx.x, t = threadIdx.x;
    if (b < 256) {
        g_deg[b * 256 + t] = 0;
    } else {
        if (t < 64) g_h1raw[t] = 0.f;
        g_hist[t] = 0;
        g_bnsum[t] = 0.f; g_bnsq[t] = 0.f;
        g_bnsum[t + 256] = 0.f; g_bnsq[t + 256] = 0.f;
    }
}
__global__ void k_zero_fnacc() {
    int i = blockIdx.x * blockDim.x + threadIdx.x;
    for (; i < 12 * NN; i += gridDim.x * blockDim.x) g_fnacc[i] = 0.f;
}

// ------------------------------- CSR build ----------------------------------
__global__ void k_deg(const int* __restrict__ ei) {
    int e = blockIdx.x * blockDim.x + threadIdx.x;
    atomicAdd(&g_deg[ei[NE + e]], 1);
}
__global__ void k_scan() {
    __shared__ int part[1024];
    int t = threadIdx.x;
    int base = t * 64;
    int s = 0;
#pragma unroll 8
    for (int i = 0; i < 64; i++) s += g_deg[base + i];
    part[t] = s;
    __syncthreads();
    for (int d = 1; d < 1024; d <<= 1) {
        int v = (t >= d) ? part[t - d] : 0;
        __syncthreads();
        part[t] += v;
        __syncthreads();
    }
    int run = part[t] - s;
    for (int i = 0; i < 64; i++) {
        g_off[base + i] = run;
        g_cur[base + i] = run;
        run += g_deg[base + i];
    }
    if (t == 1023) g_off[NN] = run;
}
__global__ void k_fill(const int* __restrict__ ei) {
    int e = blockIdx.x * blockDim.x + threadIdx.x;
    int d = ei[NE + e];
    int pos = atomicAdd(&g_cur[d], 1);
    g_csr[pos] = e;
}

// ------------------ atom embedding (+ split-A for MLP GEMM) -----------------
__global__ void k_embed(const int* __restrict__ xa, const float* __restrict__ emb) {
    int n = blockIdx.x * 8 + (threadIdx.x >> 5);
    int lane = threadIdx.x & 31;
    float4 a0 = make_float4(0.f, 0.f, 0.f, 0.f);
    float4 a1 = make_float4(0.f, 0.f, 0.f, 0.f);
#pragma unroll
    for (int f = 0; f < 9; f++) {
        int v = xa[n * 9 + f];
        const float4* row = (const float4*)(emb + ((size_t)(f * 128 + v)) * DD);
        float4 b0 = row[lane * 2], b1 = row[lane * 2 + 1];
        a0.x += b0.x; a0.y += b0.y; a0.z += b0.z; a0.w += b0.w;
        a1.x += b1.x; a1.y += b1.y; a1.z += b1.z; a1.w += b1.w;
    }
    float4* out = (float4*)(g_x + (size_t)n * DD);
    out[lane * 2] = a0; out[lane * 2 + 1] = a1;
    storeA_row(n, lane, a0, a1);
}

// ------- pack the 4 small-MLP first layers into [256,128] + head pack -------
__global__ void k_packW(const float* __restrict__ cw1, const float* __restrict__ cb1,
                        const float* __restrict__ fw1, const float* __restrict__ fb1,
                        const float* __restrict__ cw2, const float* __restrict__ cb2,
                        const float* __restrict__ fw2, const float* __restrict__ fb2) {
    int idx = blockIdx.x * blockDim.x + threadIdx.x;
    if (idx >= DD * 128) return;
    int k = idx >> 7, u = idx & 127;
    float v = 0.f;
    if (u < CHID) v = cw1[k * CHID + u];
    else if (u < 80) {
        int i = (u - CHID) / CHID, j = (u - CHID) % CHID;
        v = fw1[((size_t)i * DD + k) * CHID + j];
    }
    g_Wall[idx] = v;
    if (k == 0) {
        float b = 0.f;
        if (u < CHID) b = cb1[u];
        else if (u < 80) { int i = (u - CHID) / CHID, j = (u - CHID) % CHID; b = fb1[i * CHID + j]; }
        g_ball[u] = b;
        float4 wp = make_float4(0.f, 0.f, 0.f, 0.f);
        if (u < 20) wp.x = cw2[u];
        else if (u < 40) wp.y = fw2[0 * CHID + (u - 20)];
        else if (u < 60) wp.z = fw2[1 * CHID + (u - 40)];
        else if (u < 80) wp.w = fw2[2 * CHID + (u - 60)];
        g_W2p[u] = wp;
        if (u == 0) {
            g_b2p[0] = cb2[0];
            g_b2p[1] = fb2[0]; g_b2p[2] = fb2[1]; g_b2p[3] = fb2[2];
            g_kapsum = 0.f; g_loss = 0.f;
        }
    }
}

// ------ pre-split ALL weight matrices into swizzled bf16 hi/lo layout -------
__global__ void k_presplit_all(const float* __restrict__ gw1, const float* __restrict__ gw2) {
    int id = blockIdx.x * blockDim.x + threadIdx.x;
    if (id >= WTOTAL) return;
    const float* src;
    int K, Nc, rem;
    if (id < WOFF_W1) {
        src = g_Wall; K = 256; Nc = 128; rem = id;
    } else if (id < WOFF_W2) {
        int rid = id - WOFF_W1;
        int l = rid >> 16; rem = rid & 65535;
        src = gw1 + (size_t)l * (DD * D2); K = 256; Nc = 512;
    } else {
        int rid = id - WOFF_W2;
        int l = rid >> 16; rem = rid & 65535;
        src = gw2 + (size_t)l * (D2 * DD); K = 512; Nc = 256;
    }
    int kw = K >> 1;
    int n = rem / kw, r2 = rem - n * kw;
    int kt = r2 >> 3, c = r2 & 7;
    int p = ((c & 1) << 2) | (((c >> 1) ^ n) & 3);
    int k0 = kt * 16 + 2 * p;
    unsigned hi, lo;
    split2(src[(size_t)k0 * Nc + n], src[(size_t)(k0 + 1) * Nc + n], hi, lo);
    g_Bh[id] = hi;
    g_Bl[id] = lo;
}

// ----------- pure-async split-bf16 GEMM (A pre-split, 3-stage) --------------
// C[M,Nc] = A[M,256] @ B + bias ; used for MLP GEMM and layer GEMM1 (K=256)
template <bool STATS, bool MLPEPI, bool RELU>
__global__ __launch_bounds__(256, 2) void k_gemm_pre(
        int Boff, const float* __restrict__ biasp, int Csel, int Nc) {
    extern __shared__ unsigned dsm[];
    unsigned* AH = dsm;             // [3][1024]
    unsigned* AL = dsm + 3072;
    unsigned* BH = dsm + 6144;
    unsigned* BL = dsm + 9216;
    __shared__ float sredS[128], sredQ[128];
    __shared__ float sred[1024];

    const int K = 256, S = 16;      // K/16 tiles
    const float* bias = MLPEPI ? g_ball : biasp;
    float* C = (Csel == 0) ? g_z1 : g_h;

    int tid = threadIdx.x;
    int bm = blockIdx.y * 128, bn = blockIdx.x * 128;
    if (STATS && tid < 128) { sredS[tid] = 0.f; sredQ[tid] = 0.f; }

    int frow = tid >> 1, foff = (tid & 1) * 4;
    const unsigned* ahs = g_Ah + (size_t)(bm + frow) * 128 + foff;
    const unsigned* als = g_Al + (size_t)(bm + frow) * 128 + foff;
    const unsigned* bhs = g_Bh + Boff + (size_t)(bn + frow) * 128 + foff;
    const unsigned* bls = g_Bl + Boff + (size_t)(bn + frow) * 128 + foff;
    int fb = frow * 8 + foff;

    int w = tid >> 5, lane = tid & 31;
    int wm = (w >> 1) * 32, wn = (w & 1) * 64;
    int qr = lane >> 2, qc = lane & 3;
    int j2 = 2 * (qc ^ (qr & 3));

    float acc[2][8][4];
#pragma unroll
    for (int mt = 0; mt < 2; mt++)
#pragma unroll
        for (int nt = 0; nt < 8; nt++)
#pragma unroll
            for (int j = 0; j < 4; j++) acc[mt][nt][j] = 0.f;

    // prologue: stages 0 and 1
#pragma unroll
    for (int s = 0; s < 2; s++) {
        int sb = s * 1024 + fb;
        cp16(&AH[sb], ahs + s * 8);
        cp16(&AL[sb], als + s * 8);
        cp16(&BH[sb], bhs + s * 8);
        cp16(&BL[sb], bls + s * 8);
        asm volatile("cp.async.commit_group;\n");
    }

#pragma unroll 1
    for (int t = 0; t < S; t++) {
        if (t + 1 < S)
            asm volatile("cp.async.wait_group 1;\n");
        else
            asm volatile("cp.async.wait_group 0;\n");
        __syncthreads();
        if (t + 2 < S) {
            int sb = ((t + 2) % 3) * 1024 + fb;
            cp16(&AH[sb], ahs + (t + 2) * 8);
            cp16(&AL[sb], als + (t + 2) * 8);
            cp16(&BH[sb], bhs + (t + 2) * 8);
            cp16(&BL[sb], bls + (t + 2) * 8);
            asm volatile("cp.async.commit_group;\n");
        }
        int st = (t % 3) * 1024;
        unsigned ah[2][4], al_[2][4];
#pragma unroll
        for (int mt = 0; mt < 2; mt++) {
            int r = wm + mt * 16 + qr;
            uint2 x0 = *(const uint2*)&AH[st + r * 8 + j2];
            uint2 x1 = *(const uint2*)&AH[st + (r + 8) * 8 + j2];
            ah[mt][0] = x0.x; ah[mt][1] = x1.x; ah[mt][2] = x0.y; ah[mt][3] = x1.y;
            uint2 y0 = *(const uint2*)&AL[st + r * 8 + j2];
            uint2 y1 = *(const uint2*)&AL[st + (r + 8) * 8 + j2];
            al_[mt][0] = y0.x; al_[mt][1] = y1.x; al_[mt][2] = y0.y; al_[mt][3] = y1.y;
        }
#pragma unroll
        for (int nt = 0; nt < 8; nt++) {
            int n = wn + nt * 8 + qr;
            uint2 bh2 = *(const uint2*)&BH[st + n * 8 + j2];
            uint2 bl2 = *(const uint2*)&BL[st + n * 8 + j2];
            unsigned bhf[2] = {bh2.x, bh2.y};
            unsigned blf[2] = {bl2.x, bl2.y};
            mma16(acc[0][nt], ah[0], bhf);
            mma16(acc[1][nt], ah[1], bhf);
            mma16(acc[0][nt], ah[0], blf);
            mma16(acc[1][nt], ah[1], blf);
            mma16(acc[0][nt], al_[0], bhf);
            mma16(acc[1][nt], al_[1], bhf);
        }
    }

    // ---------------- epilogue ----------------
    float psum[16], psq[16];
    if (STATS) {
#pragma unroll
        for (int j = 0; j < 16; j++) { psum[j] = 0.f; psq[j] = 0.f; }
    }
    float racc[4][4];
    if (MLPEPI) {
#pragma unroll
        for (int s = 0; s < 4; s++)
#pragma unroll
            for (int o = 0; o < 4; o++) racc[s][o] = 0.f;
    }
#pragma unroll
    for (int nt = 0; nt < 8; nt++) {
        int cc0 = wn + nt * 8 + qc * 2;
        int col0 = bn + cc0;
        float bv0 = bias[col0], bv1 = bias[col0 + 1];
#pragma unroll
        for (int mt = 0; mt < 2; mt++) {
            int row0 = bm + wm + mt * 16 + qr;
            float v00 = acc[mt][nt][0] + bv0;
            float v01 = acc[mt][nt][1] + bv1;
            float v10 = acc[mt][nt][2] + bv0;
            float v11 = acc[mt][nt][3] + bv1;
            if (RELU) {
                v00 = fmaxf(v00, 0.f); v01 = fmaxf(v01, 0.f);
                v10 = fmaxf(v10, 0.f); v11 = fmaxf(v11, 0.f);
            }
            if (STATS) {
                psum[nt * 2 + 0] += v00 + v10;
                psum[nt * 2 + 1] += v01 + v11;
                psq[nt * 2 + 0] += v00 * v00 + v10 * v10;
                psq[nt * 2 + 1] += v01 * v01 + v11 * v11;
            }
            if (MLPEPI) {
                float4 w0 = g_W2p[cc0], w1 = g_W2p[cc0 + 1];
                racc[mt * 2 + 0][0] += v00 * w0.x + v01 * w1.x;
                racc[mt * 2 + 0][1] += v00 * w0.y + v01 * w1.y;
                racc[mt * 2 + 0][2] += v00 * w0.z + v01 * w1.z;
                racc[mt * 2 + 0][3] += v00 * w0.w + v01 * w1.w;
                racc[mt * 2 + 1][0] += v10 * w0.x + v11 * w1.x;
                racc[mt * 2 + 1][1] += v10 * w0.y + v11 * w1.y;
                racc[mt * 2 + 1][2] += v10 * w0.z + v11 * w1.z;
                racc[mt * 2 + 1][3] += v10 * w0.w + v11 * w1.w;
            } else {
                *(float2*)(C + (size_t)row0 * Nc + col0) = make_float2(v00, v01);
                *(float2*)(C + (size_t)(row0 + 8) * Nc + col0) = make_float2(v10, v11);
            }
        }
    }
    if (MLPEPI) {
#pragma unroll
        for (int s = 0; s < 4; s++)
#pragma unroll
            for (int o = 0; o < 4; o++) {
                racc[s][o] += __shfl_xor_sync(0xffffffff, racc[s][o], 1);
                racc[s][o] += __shfl_xor_sync(0xffffffff, racc[s][o], 2);
            }
        __syncthreads();
        if ((lane & 3) == 0) {
#pragma unroll
            for (int s = 0; s < 4; s++) {
                int row = wm + (s >> 1) * 16 + qr + (s & 1) * 8;
#pragma unroll
                for (int o = 0; o < 4; o++)
                    sred[row * 8 + (w & 1) * 4 + o] = racc[s][o];
            }
        }
        __syncthreads();
        if (tid < 128) {
            float o0 = sred[tid * 8 + 0] + sred[tid * 8 + 4] + g_b2p[0];
            float o1 = sred[tid * 8 + 1] + sred[tid * 8 + 5] + g_b2p[1];
            float o2 = sred[tid * 8 + 2] + sred[tid * 8 + 6] + g_b2p[2];
            float o3 = sred[tid * 8 + 3] + sred[tid * 8 + 7] + g_b2p[3];
            int row = bm + tid;
            float kap = sigmoidf_(o0);
            g_kappa[row] = kap;
            g_f[row] = sigmoidf_(o1);
            g_f[NN + row] = sigmoidf_(o2);
            g_f[2 * NN + row] = sigmoidf_(o3);
            float kp = kap;
#pragma unroll
            for (int off = 16; off > 0; off >>= 1)
                kp += __shfl_xor_sync(0xffffffff, kp, off);
            if (lane == 0) atomicAdd(&g_kapsum, kp);
        }
    }
    if (STATS) {
#pragma unroll
        for (int j = 0; j < 16; j++) {
#pragma unroll
            for (int off = 4; off < 32; off <<= 1) {
                psum[j] += __shfl_xor_sync(0xffffffff, psum[j], off);
                psq[j] += __shfl_xor_sync(0xffffffff, psq[j], off);
            }
        }
        if (lane < 4) {
#pragma unroll
            for (int nt = 0; nt < 8; nt++) {
#pragma unroll
                for (int h = 0; h < 2; h++) {
                    int cl = wn + nt * 8 + lane * 2 + h;
                    atomicAdd(&sredS[cl], psum[nt * 2 + h]);
                    atomicAdd(&sredQ[cl], psq[nt * 2 + h]);
                }
            }
        }
        __syncthreads();
        if (tid < 128) {
            atomicAdd(&g_bnsum[bn + tid], sredS[tid]);
            atomicAdd(&g_bnsq[bn + tid], sredQ[tid]);
        }
    }
}

// --------- legacy GEMM with A-transform (GEMM2: relu(BN(z1)) @ W2) ----------
__device__ __forceinline__ float4 loadA2(const float* __restrict__ A, size_t rowoff, int col) {
    float4 va = *(const float4*)(A + rowoff + col);
    float4 sc = *(const float4*)(g_scale + col);
    float4 bb = *(const float4*)(g_bias + col);
    va.x = fmaxf(va.x * sc.x + bb.x, 0.f);
    va.y = fmaxf(va.y * sc.y + bb.y, 0.f);
    va.z = fmaxf(va.z * sc.z + bb.z, 0.f);
    va.w = fmaxf(va.w * sc.w + bb.w, 0.f);
    return va;
}

__global__ __launch_bounds__(256, 2) void k_gemm2(
        int Boff, const float* __restrict__ biasp, int Nc, int K) {
    __shared__ unsigned Ahs[2][128][8], Als[2][128][8];
    __shared__ unsigned Bhs[2][128][8], Bls[2][128][8];
    __shared__ float sredS[128], sredQ[128];

    const float* A = g_z1;
    float* C = g_h;

    int tid = threadIdx.x;
    int bm = blockIdx.y * 128, bn = blockIdx.x * 128;
    if (tid < 128) { sredS[tid] = 0.f; sredQ[tid] = 0.f; }

    int aRow = tid >> 2, aP0 = (tid & 3) * 2;
    int aCol0 = aP0 * 2;
    int r3f = aRow & 3;
    int cA0 = 2 * ((aP0 & 3) ^ r3f) + (aP0 >> 2);
    int cA1 = 2 * (((aP0 + 1) & 3) ^ r3f) + ((aP0 + 1) >> 2);
    size_t aoff0 = (size_t)(bm + aRow) * K;
    size_t aoff1 = (size_t)(bm + aRow + 64) * K;
    int nl = tid >> 1, halfB = (tid & 1) * 4;
    const unsigned* bhsrc = g_Bh + Boff + (size_t)(bn + nl) * (K >> 1) + halfB;
    const unsigned* blsrc = g_Bl + Boff + (size_t)(bn + nl) * (K >> 1) + halfB;

    int w = tid >> 5, lane = tid & 31;
    int wm = (w >> 1) * 32, wn = (w & 1) * 64;
    int qr = lane >> 2, qc = lane & 3;
    int j2 = 2 * (qc ^ (qr & 3));

    float acc[2][8][4];
#pragma unroll
    for (int mt = 0; mt < 2; mt++)
#pragma unroll
        for (int nt = 0; nt < 8; nt++)
#pragma unroll
            for (int j = 0; j < 4; j++) acc[mt][nt][j] = 0.f;

    float4 va0, va1;
    unsigned th, tl;

    cp16(&Bhs[0][nl][halfB], bhsrc);
    cp16(&Bls[0][nl][halfB], blsrc);
    asm volatile("cp.async.commit_group;\n");
    va0 = loadA2(A, aoff0, aCol0);
    va1 = loadA2(A, aoff1, aCol0);
    split2(va0.x, va0.y, th, tl); Ahs[0][aRow][cA0] = th; Als[0][aRow][cA0] = tl;
    split2(va0.z, va0.w, th, tl); Ahs[0][aRow][cA1] = th; Als[0][aRow][cA1] = tl;
    split2(va1.x, va1.y, th, tl); Ahs[0][aRow + 64][cA0] = th; Als[0][aRow + 64][cA0] = tl;
    split2(va1.z, va1.w, th, tl); Ahs[0][aRow + 64][cA1] = th; Als[0][aRow + 64][cA1] = tl;
    asm volatile("cp.async.wait_group 0;\n");
    __syncthreads();

    int buf = 0;
#pragma unroll 1
    for (int k0 = 0; k0 < K; k0 += 16) {
        int kn = k0 + 16;
        if (kn < K) {
            cp16(&Bhs[buf ^ 1][nl][halfB], bhsrc + (kn >> 1));
            cp16(&Bls[buf ^ 1][nl][halfB], blsrc + (kn >> 1));
            asm volatile("cp.async.commit_group;\n");
            va0 = loadA2(A, aoff0, kn + aCol0);
            va1 = loadA2(A, aoff1, kn + aCol0);
        }
        unsigned ah[2][4], al_[2][4];
#pragma unroll
        for (int mt = 0; mt < 2; mt++) {
            int r = wm + mt * 16 + qr;
            uint2 x0 = *(const uint2*)&Ahs[buf][r][j2];
            uint2 x1 = *(const uint2*)&Ahs[buf][r + 8][j2];
            ah[mt][0] = x0.x; ah[mt][1] = x1.x; ah[mt][2] = x0.y; ah[mt][3] = x1.y;
            uint2 y0 = *(const uint2*)&Als[buf][r][j2];
            uint2 y1 = *(const uint2*)&Als[buf][r + 8][j2];
            al_[mt][0] = y0.x; al_[mt][1] = y1.x; al_[mt][2] = y0.y; al_[mt][3] = y1.y;
        }
#pragma unroll
        for (int nt = 0; nt < 8; nt++) {
            int n = wn + nt * 8 + qr;
            uint2 bh2 = *(const uint2*)&Bhs[buf][n][j2];
            uint2 bl2 = *(const uint2*)&Bls[buf][n][j2];
            unsigned bhf[2] = {bh2.x, bh2.y};
            unsigned blf[2] = {bl2.x, bl2.y};
            mma16(acc[0][nt], ah[0], bhf);
            mma16(acc[1][nt], ah[1], bhf);
            mma16(acc[0][nt], ah[0], blf);
            mma16(acc[1][nt], ah[1], blf);
            mma16(acc[0][nt], al_[0], bhf);
            mma16(acc[1][nt], al_[1], bhf);
        }
        if (kn < K) {
            int nb = buf ^ 1;
            split2(va0.x, va0.y, th, tl); Ahs[nb][aRow][cA0] = th; Als[nb][aRow][cA0] = tl;
            split2(va0.z, va0.w, th, tl); Ahs[nb][aRow][cA1] = th; Als[nb][aRow][cA1] = tl;
            split2(va1.x, va1.y, th, tl); Ahs[nb][aRow + 64][cA0] = th; Als[nb][aRow + 64][cA0] = tl;
            split2(va1.z, va1.w, th, tl); Ahs[nb][aRow + 64][cA1] = th; Als[nb][aRow + 64][cA1] = tl;
            asm volatile("cp.async.wait_group 0;\n");
            __syncthreads();
            buf ^= 1;
        }
    }

    float psum[16], psq[16];
#pragma unroll
    for (int j = 0; j < 16; j++) { psum[j] = 0.f; psq[j] = 0.f; }
#pragma unroll
    for (int nt = 0; nt < 8; nt++) {
        int cc0 = wn + nt * 8 + qc * 2;
        int col0 = bn + cc0;
        float bv0 = biasp[col0], bv1 = biasp[col0 + 1];
#pragma unroll
        for (int mt = 0; mt < 2; mt++) {
            int row0 = bm + wm + mt * 16 + qr;
            float v00 = acc[mt][nt][0] + bv0;
            float v01 = acc[mt][nt][1] + bv1;
            float v10 = acc[mt][nt][2] + bv0;
            float v11 = acc[mt][nt][3] + bv1;
            psum[nt * 2 + 0] += v00 + v10;
            psum[nt * 2 + 1] += v01 + v11;
            psq[nt * 2 + 0] += v00 * v00 + v10 * v10;
            psq[nt * 2 + 1] += v01 * v01 + v11 * v11;
            *(float2*)(C + (size_t)row0 * Nc + col0) = make_float2(v00, v01);
            *(float2*)(C + (size_t)(row0 + 8) * Nc + col0) = make_float2(v10, v11);
        }
    }
#pragma unroll
    for (int j = 0; j < 16; j++) {
#pragma unroll
        for (int off = 4; off < 32; off <<= 1) {
            psum[j] += __shfl_xor_sync(0xffffffff, psum[j], off);
            psq[j] += __shfl_xor_sync(0xffffffff, psq[j], off);
        }
    }
    if (lane < 4) {
#pragma unroll
        for (int nt = 0; nt < 8; nt++) {
#pragma unroll
            for (int h = 0; h < 2; h++) {
                int cl = wn + nt * 8 + lane * 2 + h;
                atomicAdd(&sredS[cl], psum[nt * 2 + h]);
                atomicAdd(&sredQ[cl], psq[nt * 2 + h]);
            }
        }
    }
    __syncthreads();
    if (tid < 128) {
        atomicAdd(&g_bnsum[bn + tid], sredS[tid]);
        atomicAdd(&g_bnsq[bn + tid], sredQ[tid]);
    }
}

// ------------------------------- WeightMLP ----------------------------------
__global__ void k_wm_reduce(const int* __restrict__ ea, const float* __restrict__ w1) {
    __shared__ float sm[4][64];
    int t = threadIdx.x, g = t >> 6, j = t & 63;
    float acc = 0.f;
    for (int e = blockIdx.x * 4 + g; e < NE; e += gridDim.x * 4) {
        float s = (float)(ea[e * 3] + ea[e * 3 + 1] + ea[e * 3 + 2]);
        acc += s * w1[(size_t)e * 64 + j];
    }
    sm[g][j] = acc;
    __syncthreads();
    if (g == 0) atomicAdd(&g_h1raw[j], sm[0][j] + sm[1][j] + sm[2][j] + sm[3][j]);
}
__global__ void k_weights(const float* __restrict__ b1, const float* __restrict__ w2,
                          const float* __restrict__ b2, const float* __restrict__ w3,
                          const float* __restrict__ b3) {
    __shared__ float h1[64], h2[64];
    int t = threadIdx.x;
    if (t < 64) h1[t] = fmaxf(g_h1raw[t] + b1[t], 0.f);
    __syncthreads();
    if (t < 64) {
        float a = b2[t];
#pragma unroll 8
        for (int k = 0; k < 64; k++) a += h1[k] * w2[k * 64 + t];
        h2[t] = fmaxf(a, 0.f);
    }
    __syncthreads();
    int e = blockIdx.x * 256 + t;
    float acc = b3[e];
#pragma unroll 8
    for (int k = 0; k < 64; k++) acc += h2[k] * w3[(size_t)k * NE + e];
    g_weights[e] = sigmoidf_(acc);
}

// -------------------- exact top-k threshold (parallel radix) ----------------
__global__ void k_rinit(const int* __restrict__ pp) {
    long long nr = (long long)NN * (long long)pp[0] / 100;
    int r = (int)((nr < 100) ? nr : 100);
    if (r < 1) r = 1;
    g_rank = r;
    g_prefix = 0;
}
__global__ void k_hist(int pass) {
    __shared__ unsigned sh[256];
    int t = threadIdx.x;
    sh[t] = 0;
    __syncthreads();
    int shift = 24 - pass * 8;
    unsigned pfx = g_prefix;
    for (int i = blockIdx.x * 256 + t; i < NN; i += gridDim.x * 256) {
        unsigned bits = __float_as_uint(g_kappa[i]);
        bool ok = (pass == 0) || ((bits >> (shift + 8)) == (pfx >> (shift + 8)));
        if (ok) atomicAdd(&sh[(bits >> shift) & 255], 1u);
    }
    __syncthreads();
    if (sh[t]) atomicAdd(&g_hist[t], sh[t]);
}
__global__ void k_rsel(int pass) {
    __shared__ unsigned h[256];
    int t = threadIdx.x;
    h[t] = g_hist[t];
    g_hist[t] = 0;
    __syncthreads();
    if (t == 0) {
        int r = g_rank;
        unsigned d = 255;
        for (;; d--) {
            unsigned c = h[d];
            if (r <= (int)c || d == 0) break;
            r -= (int)c;
        }
        g_rank = r;
        g_prefix |= (d << (24 - pass * 8));
    }
}
__global__ void k_ew(const int* __restrict__ ei) {
    int e = blockIdx.x * blockDim.x + threadIdx.x;
    unsigned thr = g_prefix;
    unsigned a = __float_as_uint(g_kappa[ei[e]]);
    unsigned b = __float_as_uint(g_kappa[ei[NE + e]]);
    g_ew[e] = (a >= thr || b >= thr) ? 1e-5f : 1.0f;
}

// ----------------------- Bakry-Emery functional passes ----------------------
__global__ void k_fnA(const int* __restrict__ ei) {
    int e = blockIdx.x * blockDim.x + threadIdx.x;
    int s = ei[e], d = ei[NE + e];
    float w = g_weights[e];
#pragma unroll
    for (int i = 0; i < 3; i++) {
        float fd = g_f[i * NN + d] - g_f[i * NN + s];
        atomicAdd(&g_fnacc[i * NN + s], 0.5f * w * fd * fd);
        atomicAdd(&g_fnacc[3 * NN + i * NN + s], w * fd);
    }
}
__global__ void k_fnB(const int* __restrict__ ei) {
    int e = blockIdx.x * blockDim.x + threadIdx.x;
    int s = ei[e], d = ei[NE + e];
    float w = g_weights[e];
#pragma unroll
    for (int i = 0; i < 3; i++) {
        float gd = g_fnacc[i * NN + d] - g_fnacc[i * NN + s];
        atomicAdd(&g_fnacc[6 * NN + i * NN + s], w * gd);
        float fd = g_f[i * NN + d] - g_f[i * NN + s];
        float dfd = g_fnacc[3 * NN + i * NN + d] - g_fnacc[3 * NN + i * NN + s];
        atomicAdd(&g_fnacc[9 * NN + i * NN + s], 0.5f * w * fd * dfd);
    }
}
__global__ void k_fnC() {
    __shared__ float red[256];
    int n = blockIdx.x * 256 + threadIdx.x;
    float kap = g_kappa[n];
    float part = 0.f;
#pragma unroll
    for (int i = 0; i < 3; i++) {
        float gam = g_fnacc[i * NN + n];
        float dg = g_fnacc[6 * NN + i * NN + n];
        float gfd = g_fnacc[9 * NN + i * NN + n];
        part += fmaxf(kap * gam - (0.5f * dg - gfd), 0.f);
    }
    red[threadIdx.x] = part;
    __syncthreads();
    for (int s = 128; s > 0; s >>= 1) { if (threadIdx.x < s) red[threadIdx.x] += red[threadIdx.x + s]; __syncthreads(); }
    if (threadIdx.x == 0) atomicAdd(&g_loss, red[0]);
}

// --- GIN message: CSR gather; writes split-swizzled A = alpha*h' + agg ------
template <int HSEL>
__global__ void k_msg2(const int* __restrict__ ei, const int* __restrict__ ea,
                       const float* __restrict__ bemb, const float* __restrict__ epsp) {
    const float* h = HSEL ? g_h : g_x;
    int n = blockIdx.x * 8 + (threadIdx.x >> 5);
    int lane = threadIdx.x & 31;
    int beg = g_off[n], end = g_off[n + 1];
    float alpha = 1.0f + epsp[0];
    float4 a0 = make_float4(0.f, 0.f, 0.f, 0.f);
    float4 a1 = make_float4(0.f, 0.f, 0.f, 0.f);
    int q = lane * 2;
    float4 sc0, bb0, sc1, bb1;
    if (HSEL) {
        sc0 = ((const float4*)g_scale2)[q];     bb0 = ((const float4*)g_bias2)[q];
        sc1 = ((const float4*)g_scale2)[q + 1]; bb1 = ((const float4*)g_bias2)[q + 1];
    }
    for (int p = beg; p < end; p++) {
        int e = g_csr[p];
        int s = ei[e];
        float w = g_ew[e];
        const float4* b0 = (const float4*)(bemb + (size_t)(0 * 8 + ea[e * 3 + 0]) * DD);
        const float4* b1 = (const float4*)(bemb + (size_t)(1 * 8 + ea[e * 3 + 1]) * DD);
        const float4* b2 = (const float4*)(bemb + (size_t)(2 * 8 + ea[e * 3 + 2]) * DD);
        const float4* hs = (const float4*)(h + (size_t)s * DD);
        float4 v = hs[q];
        if (HSEL) {
            v.x = fmaxf(v.x * sc0.x + bb0.x, 0.f);
            v.y = fmaxf(v.y * sc0.y + bb0.y, 0.f);
            v.z = fmaxf(v.z * sc0.z + bb0.z, 0.f);
            v.w = fmaxf(v.w * sc0.w + bb0.w, 0.f);
        }
        float4 x0 = b0[q], x1 = b1[q], x2 = b2[q];
        a0.x += fmaxf(v.x + x0.x + x1.x + x2.x, 0.f) * w;
        a0.y += fmaxf(v.y + x0.y + x1.y + x2.y, 0.f) * w;
        a0.z += fmaxf(v.z + x0.z + x1.z + x2.z, 0.f) * w;
        a0.w += fmaxf(v.w + x0.w + x1.w + x2.w, 0.f) * w;
        v = hs[q + 1];
        if (HSEL) {
            v.x = fmaxf(v.x * sc1.x + bb1.x, 0.f);
            v.y = fmaxf(v.y * sc1.y + bb1.y, 0.f);
            v.z = fmaxf(v.z * sc1.z + bb1.z, 0.f);
            v.w = fmaxf(v.w * sc1.w + bb1.w, 0.f);
        }
        x0 = b0[q + 1]; x1 = b1[q + 1]; x2 = b2[q + 1];
        a1.x += fmaxf(v.x + x0.x + x1.x + x2.x, 0.f) * w;
        a1.y += fmaxf(v.y + x0.y + x1.y + x2.y, 0.f) * w;
        a1.z += fmaxf(v.z + x0.z + x1.z + x2.z, 0.f) * w;
        a1.w += fmaxf(v.w + x0.w + x1.w + x2.w, 0.f) * w;
    }
    // own row: A = alpha*h'(n) + agg
    const float4* hown = (const float4*)(h + (size_t)n * DD);
    float4 o0 = hown[q], o1 = hown[q + 1];
    if (HSEL) {
        o0.x = fmaxf(o0.x * sc0.x + bb0.x, 0.f);
        o0.y = fmaxf(o0.y * sc0.y + bb0.y, 0.f);
        o0.z = fmaxf(o0.z * sc0.z + bb0.z, 0.f);
        o0.w = fmaxf(o0.w * sc0.w + bb0.w, 0.f);
        o1.x = fmaxf(o1.x * sc1.x + bb1.x, 0.f);
        o1.y = fmaxf(o1.y * sc1.y + bb1.y, 0.f);
        o1.z = fmaxf(o1.z * sc1.z + bb1.z, 0.f);
        o1.w = fmaxf(o1.w * sc1.w + bb1.w, 0.f);
    }
    a0.x += alpha * o0.x; a0.y += alpha * o0.y; a0.z += alpha * o0.z; a0.w += alpha * o0.w;
    a1.x += alpha * o1.x; a1.y += alpha * o1.y; a1.z += alpha * o1.z; a1.w += alpha * o1.w;
    storeA_row(n, lane, a0, a1);
}

// ----------------------------- BN final + apply -----------------------------
__global__ void k_bnfinal(const float* __restrict__ g, const float* __restrict__ b) {
    int c = threadIdx.x;
    float mean = g_bnsum[c] * (1.0f / NN);
    float var = g_bnsq[c] * (1.0f / NN) - mean * mean;
    float inv = rsqrtf(var + 1e-5f);
    float sc = g[c] * inv;
    g_scale[c] = sc;
    g_bias[c] = b[c] - mean * sc;
    g_bnsum[c] = 0.f;
    g_bnsq[c] = 0.f;
}
__global__ void k_bnfinal2(const float* __restrict__ g, const float* __restrict__ b) {
    int c = threadIdx.x;
    float mean = g_bnsum[c] * (1.0f / NN);
    float var = g_bnsq[c] * (1.0f / NN) - mean * mean;
    float inv = rsqrtf(var + 1e-5f);
    float sc = g[c] * inv;
    g_scale2[c] = sc;
    g_bias2[c] = b[c] - mean * sc;
    g_bnsum[c] = 0.f;
    g_bnsq[c] = 0.f;
}
__global__ void k_bnapply(float* __restrict__ dout) {
    int i = blockIdx.x * blockDim.x + threadIdx.x;
    float4 v = ((const float4*)g_h)[i];
    int cb = i & (DD / 4 - 1);
    float4 sc = ((const float4*)g_scale2)[cb];
    float4 bb = ((const float4*)g_bias2)[cb];
    v.x = v.x * sc.x + bb.x; v.y = v.y * sc.y + bb.y;
    v.z = v.z * sc.z + bb.z; v.w = v.w * sc.w + bb.w;
    ((float4*)dout)[i] = v;
}
__global__ void k_final(float* __restrict__ dout, int write) {
    if (write) dout[(size_t)NN * DD] = g_loss - 3.0f * g_kapsum;
}

// --------------------------------- launcher ---------------------------------
extern "C" void kernel_launch(void* const* d_in, const int* in_sizes, int n_in,
                              void* d_out, int out_size) {
    const int*   xa   = (const int*)d_in[0];
    const int*   ei   = (const int*)d_in[1];
    const int*   ea   = (const int*)d_in[2];
    const int*   pp   = (const int*)d_in[3];
    const float* aemb = (const float*)d_in[4];
    const float* bemb = (const float*)d_in[5];
    const float* gw1  = (const float*)d_in[6];
    const float* gb1  = (const float*)d_in[7];
    const float* gbng = (const float*)d_in[8];
    const float* gbnb = (const float*)d_in[9];
    const float* gw2  = (const float*)d_in[10];
    const float* gb2  = (const float*)d_in[11];
    const float* geps = (const float*)d_in[12];
    const float* bng  = (const float*)d_in[13];
    const float* bnb  = (const float*)d_in[14];
    const float* cw1  = (const float*)d_in[15];
    const float* cb1  = (const float*)d_in[16];
    const float* cw2  = (const float*)d_in[17];
    const float* cb2  = (const float*)d_in[18];
    const float* fw1  = (const float*)d_in[19];
    const float* fb1  = (const float*)d_in[20];
    const float* fw2  = (const float*)d_in[21];
    const float* fb2  = (const float*)d_in[22];
    const float* wmw1 = (const float*)d_in[23];
    const float* wmb1 = (const float*)d_in[24];
    const float* wmw2 = (const float*)d_in[25];
    const float* wmb2 = (const float*)d_in[26];
    const float* wmw3 = (const float*)d_in[27];
    const float* wmb3 = (const float*)d_in[28];
    float* out = (float*)d_out;

    cudaFuncSetAttribute(k_gemm_pre<false, true, true>,
                         cudaFuncAttributeMaxDynamicSharedMemorySize, DSMSZ);
    cudaFuncSetAttribute(k_gemm_pre<true, false, false>,
                         cudaFuncAttributeMaxDynamicSharedMemorySize, DSMSZ);

    // launches 1-3, then #4 = MLP GEMM (ncu captures launch #4)
    k_packW<<<(DD * 128 + 255) / 256, 256>>>(cw1, cb1, fw1, fb1, cw2, cb2, fw2, fb2);
    k_presplit_all<<<(WTOTAL + 255) / 256, 256>>>(gw1, gw2);
    k_embed<<<NN / 8, 256>>>(xa, aemb);
    k_gemm_pre<false, true, true><<<dim3(1, NN / 128), 256, DSMSZ>>>(WOFF_WALL, nullptr, 0, 128);

    k_zero_init<<<257, 256>>>();
    k_deg<<<NE / 256, 256>>>(ei);
    k_scan<<<1, 1024>>>();
    k_fill<<<NE / 256, 256>>>(ei);
    k_wm_reduce<<<512, 256>>>(ea, wmw1);
    k_weights<<<NE / 256, 256>>>(wmb1, wmw2, wmb2, wmw3, wmb3);
    k_rinit<<<1, 1>>>(pp);
    for (int p = 0; p < 4; p++) {
        k_hist<<<64, 256>>>(p);
        k_rsel<<<1, 256>>>(p);
    }
    k_ew<<<NE / 256, 256>>>(ei);
    k_zero_fnacc<<<768, 256>>>();
    k_fnA<<<NE / 256, 256>>>(ei);
    k_fnB<<<NE / 256, 256>>>(ei);
    k_fnC<<<NN / 256, 256>>>();

    for (int l = 0; l < 3; l++) {
        if (l == 0)
            k_msg2<0><<<NN / 8, 256>>>(ei, ea, bemb + (size_t)l * 3 * 8 * DD, geps + l);
        else
            k_msg2<1><<<NN / 8, 256>>>(ei, ea, bemb + (size_t)l * 3 * 8 * DD, geps + l);
        k_gemm_pre<true, false, false><<<dim3(D2 / 128, NN / 128), 256, DSMSZ>>>(
            WOFF_W1 + l * 65536, gb1 + l * D2, 0, D2);
        k_bnfinal<<<1, D2>>>(gbng + l * D2, gbnb + l * D2);
        k_gemm2<<<dim3(DD / 128, NN / 128), 256>>>(
            WOFF_W2 + l * 65536, gb2 + l * DD, DD, D2);
        k_bnfinal2<<<1, DD>>>(bng + l * DD, bnb + l * DD);
    }
    k_bnapply<<<NN * DD / 4 / 256, 256>>>(out);
    k_final<<<1, 1>>>(out, (out_size > NN * DD) ? 1 : 0);
}